// round 10
// baseline (speedup 1.0000x reference)
#include <cuda_runtime.h>
#include <cstdint>

// Problem constants
#define S_LEN 2048
#define EMB   1024
#define HEADS 16
#define DH    64
#define BATCH 2

// Scratch (no allocations allowed)
__device__ float g_qkv[(size_t)BATCH * S_LEN * 3 * EMB];   // [B,S,3E]
__device__ float g_ctx[(size_t)BATCH * S_LEN * EMB];       // [B,S,E] (tf32-rounded)
__device__ float g_xr [(size_t)BATCH * S_LEN * EMB];       // rounded x
__device__ float g_wir[(size_t)3 * EMB * EMB];             // rounded in_proj_w
__device__ float g_wor[(size_t)EMB * EMB];                 // rounded out_proj_w

// ===========================================================================
// Helpers
// ===========================================================================
__device__ __forceinline__ uint32_t smem_u32(const void* p) {
    uint32_t a;
    asm("{ .reg .u64 t; cvta.to.shared.u64 t, %1; cvt.u32.u64 %0, t; }"
        : "=r"(a) : "l"(p));
    return a;
}

__device__ __forceinline__ void cp_async16(uint32_t dst, const void* src) {
    asm volatile("cp.async.cg.shared.global [%0], [%1], 16;"
                 :: "r"(dst), "l"(src));
}
#define CP_COMMIT() asm volatile("cp.async.commit_group;")
#define CP_WAIT1()  asm volatile("cp.async.wait_group 1;")
#define CP_WAIT0()  asm volatile("cp.async.wait_group 0;")

__device__ __forceinline__ uint32_t f2tf32(float f) {
    uint32_t r;
    asm("cvt.rna.tf32.f32 %0, %1;" : "=r"(r) : "f"(f));
    return r;
}
__device__ __forceinline__ float rnd_tf32(float f) {
    return __uint_as_float(f2tf32(f));
}

// bf16 round-to-nearest-even "hi" part of an fp32 (exact bf16 value as fp32)
__device__ __forceinline__ float bf16_hi(float x) {
    uint32_t xb = __float_as_uint(x);
    uint32_t hb = (xb + 0x7fffu + ((xb >> 16) & 1u)) & 0xffff0000u;
    return __uint_as_float(hb);
}
// Pack two fp32 -> bf16x2 register: e0 -> low half (lower k index), e1 -> high
__device__ __forceinline__ uint32_t pack2_bf16(float e0, float e1) {
    uint32_t r;
    asm("cvt.rn.bf16x2.f32 %0, %1, %2;" : "=r"(r) : "f"(e1), "f"(e0));
    return r;
}

// mma.sync m16n8k8 tf32: D += A*B, fp32 accumulate
__device__ __forceinline__ void mma_tf32(
    float* c, const uint32_t* a, const uint32_t* b)
{
    asm volatile(
        "mma.sync.aligned.m16n8k8.row.col.f32.tf32.tf32.f32 "
        "{%0,%1,%2,%3}, {%4,%5,%6,%7}, {%8,%9}, {%0,%1,%2,%3};"
        : "+f"(c[0]), "+f"(c[1]), "+f"(c[2]), "+f"(c[3])
        : "r"(a[0]), "r"(a[1]), "r"(a[2]), "r"(a[3]), "r"(b[0]), "r"(b[1]));
}

// mma.sync m16n8k16 bf16: D += A*B, fp32 accumulate
__device__ __forceinline__ void mma_bf16(
    float* c, const uint32_t* a, const uint32_t* b)
{
    asm volatile(
        "mma.sync.aligned.m16n8k16.row.col.f32.bf16.bf16.f32 "
        "{%0,%1,%2,%3}, {%4,%5,%6,%7}, {%8,%9}, {%0,%1,%2,%3};"
        : "+f"(c[0]), "+f"(c[1]), "+f"(c[2]), "+f"(c[3])
        : "r"(a[0]), "r"(a[1]), "r"(a[2]), "r"(a[3]), "r"(b[0]), "r"(b[1]));
}

// ===========================================================================
// Elementwise tf32 pre-rounding (RNA). Idempotent; feeds GEMMs raw bits.
// ===========================================================================
__global__ __launch_bounds__(256) void round_tf32_kernel(
    const float4* __restrict__ src, float4* __restrict__ dst, int n4)
{
    for (int i = blockIdx.x * 256 + threadIdx.x; i < n4; i += gridDim.x * 256) {
        float4 v = src[i];
        v.x = rnd_tf32(v.x); v.y = rnd_tf32(v.y);
        v.z = rnd_tf32(v.z); v.w = rnd_tf32(v.w);
        dst[i] = v;
    }
}

// ===========================================================================
// tf32 tensor-core GEMM on PRE-ROUNDED inputs (unchanged):
//   C[M,N] = A[M,K] @ B[N,K]^T + bias[N]
// ===========================================================================
#define PAD     36
#define TILE_F  (128 * PAD)
#define BUF_F   (2 * TILE_F)
#define GM_SMEM (2 * BUF_F * 4)

__global__ __launch_bounds__(256, 2) void gemm_mma(
    const float* __restrict__ A, const float* __restrict__ B,
    const float* __restrict__ bias, float* __restrict__ C,
    int M, int N, int K)
{
    extern __shared__ float smem[];
    const int tid  = threadIdx.x;
    const int wid  = tid >> 5;
    const int lane = tid & 31;
    const int wm   = wid >> 2;
    const int wn   = wid & 3;
    const int g    = lane >> 2;
    const int tig  = lane & 3;
    const int bm   = blockIdx.y * 128;
    const int bn   = blockIdx.x * 128;

    float acc[4][4][4];
    #pragma unroll
    for (int mt = 0; mt < 4; mt++)
        #pragma unroll
        for (int nt = 0; nt < 4; nt++)
            #pragma unroll
            for (int i = 0; i < 4; i++)
                acc[mt][nt][i] = 0.0f;

    auto fill = [&](int buf, int kc) {
        const int k0 = kc << 5;
        const uint32_t sA = smem_u32(smem + buf * BUF_F);
        const uint32_t sB = sA + TILE_F * 4;
        #pragma unroll
        for (int i = 0; i < 4; i++) {
            const int id = tid + (i << 8);
            const int r  = id >> 3;
            const int c  = id & 7;
            const uint32_t so = (uint32_t)(r * PAD + c * 4) * 4;
            cp_async16(sA + so, A + (size_t)(bm + r) * K + k0 + c * 4);
            cp_async16(sB + so, B + (size_t)(bn + r) * K + k0 + c * 4);
        }
        CP_COMMIT();
    };

    const int NK = K >> 5;
    fill(0, 0);
    fill(1, 1);

    for (int kc = 0; kc < NK; kc++) {
        const int buf = kc & 1;
        if (kc == NK - 1) { CP_WAIT0(); } else { CP_WAIT1(); }
        __syncthreads();

        const float* sA = smem + buf * BUF_F;
        const float* sB = sA + TILE_F;

        #pragma unroll
        for (int ks = 0; ks < 4; ks++) {
            const int kb = ks * 8 + tig;
            uint32_t af[4][4], bf[4][2];
            #pragma unroll
            for (int mt = 0; mt < 4; mt++) {
                const float* p = sA + (wm * 64 + mt * 16 + g) * PAD + kb;
                af[mt][0] = __float_as_uint(p[0]);
                af[mt][1] = __float_as_uint(p[8 * PAD]);
                af[mt][2] = __float_as_uint(p[4]);
                af[mt][3] = __float_as_uint(p[8 * PAD + 4]);
            }
            #pragma unroll
            for (int nt = 0; nt < 4; nt++) {
                const float* p = sB + (wn * 32 + nt * 8 + g) * PAD + kb;
                bf[nt][0] = __float_as_uint(p[0]);
                bf[nt][1] = __float_as_uint(p[4]);
            }
            #pragma unroll
            for (int mt = 0; mt < 4; mt++)
                #pragma unroll
                for (int nt = 0; nt < 4; nt++)
                    mma_tf32(acc[mt][nt], af[mt], bf[nt]);
        }
        __syncthreads();

        if (kc + 2 < NK) fill(buf, kc + 2);
    }

    #pragma unroll
    for (int mt = 0; mt < 4; mt++) {
        const int row0 = bm + wm * 64 + mt * 16 + g;
        #pragma unroll
        for (int nt = 0; nt < 4; nt++) {
            const int col = bn + wn * 32 + nt * 8 + 2 * tig;
            const float b0 = bias[col], b1 = bias[col + 1];
            float2 o0, o1;
            o0.x = acc[mt][nt][0] + b0;  o0.y = acc[mt][nt][1] + b1;
            o1.x = acc[mt][nt][2] + b0;  o1.y = acc[mt][nt][3] + b1;
            *(float2*)(C + (size_t)row0 * N + col)       = o0;
            *(float2*)(C + (size_t)(row0 + 8) * N + col) = o1;
        }
    }
}

// ===========================================================================
// Tensor-core flash attention, compensated BF16 (m16n8k16), 2-DEEP PIPELINE.
// Same math as round 9. Change: raw landing AND packed hi/lo buffers are both
// double-buffered, so KV load for tile kt+1 is always in flight while tile kt
// is converted+consumed (round 9 was 1-deep and exposed DRAM latency/tile).
// Loop: wait(kt) -> convert raw[b]->packed[b] -> sync -> issue fill(kt+2) into
// freed raw[b] -> mma/softmax on packed[b].
// ===========================================================================
#define AP        68                            // padded raw row (floats)
#define QT_F      (128 * AP)                    // 8704 floats
#define KVT_F     (64 * AP)                     // 4352 floats
#define A_RAW     QT_F                          // raw: [K0 V0 K1 V1]
#define PK_W      33                            // packed row stride (words)
#define PKBUF_W   (4 * 64 * PK_W)               // KH,KL,VH,VL per buffer = 8448
#define A_PACK    (QT_F + 4 * KVT_F)            // word offset of packed area
#define ATT_SMEM  ((A_PACK + 2 * PKBUF_W) * 4)  // 172032 bytes

__global__ __launch_bounds__(256) void attn_mma_kernel(
    const float* __restrict__ qkv, float* __restrict__ ctx)
{
    extern __shared__ float smem[];
    const int tid  = threadIdx.x;
    const int w    = tid >> 5;
    const int lane = tid & 31;
    const int g    = lane >> 2;
    const int tig  = lane & 3;

    const int qt = gridDim.x - 1 - blockIdx.x;     // heaviest tiles first
    const int bh = blockIdx.y;
    const int b  = bh >> 4;
    const int h  = bh & 15;

    const float* base = qkv + (size_t)b * S_LEN * (3 * EMB);
    const int ktmax = 2 * qt + 1;

    // ---- issue Q stage (bundled into first KV group) ----
    {
        const float* Qsrc = base + (size_t)(qt * 128) * (3 * EMB) + h * DH;
        const uint32_t qs = smem_u32(smem);
        #pragma unroll
        for (int i = 0; i < 8; i++) {
            const int id = tid + (i << 8);
            const int r = id >> 4, c4 = id & 15;
            cp_async16(qs + (uint32_t)((r * AP + c4 * 4) * 4),
                       Qsrc + (size_t)r * (3 * EMB) + c4 * 4);
        }
    }

    auto fill_kv = [&](int kt) {
        const int buf = kt & 1;
        const float* Ksrc = base + (size_t)(kt * 64) * (3 * EMB) + EMB + h * DH;
        const float* Vsrc = Ksrc + EMB;
        const uint32_t kd = smem_u32(smem + A_RAW + buf * 2 * KVT_F);
        const uint32_t vd = kd + KVT_F * 4;
        #pragma unroll
        for (int i = 0; i < 4; i++) {
            const int id = tid + (i << 8);
            const int r = id >> 4, c4 = id & 15;
            const uint32_t so = (uint32_t)((r * AP + c4 * 4) * 4);
            const size_t go = (size_t)r * (3 * EMB) + c4 * 4;
            cp_async16(kd + so, Ksrc + go);
            cp_async16(vd + so, Vsrc + go);
        }
        CP_COMMIT();
    };

    fill_kv(0);          // group 0: Q + KV(0)
    fill_kv(1);          // group 1: KV(1)   (ktmax >= 1 always)

    uint32_t Qh[4][4], Ql[4][4];
    float S[8][4];
    float O[8][4];
    float m0 = -1e30f, m1 = -1e30f, l0 = 0.0f, l1 = 0.0f;
    #pragma unroll
    for (int nt = 0; nt < 8; nt++)
        #pragma unroll
        for (int i = 0; i < 4; i++)
            O[nt][i] = 0.0f;

    for (int kt = 0; kt <= ktmax; kt++) {
        const int buf = kt & 1;
        if (kt < ktmax) { CP_WAIT1(); } else { CP_WAIT0(); }
        __syncthreads();   // raw[buf] landed; packed[buf] free (consumed kt-2)

        uint32_t* const KH = (uint32_t*)smem + A_PACK + buf * PKBUF_W;
        uint32_t* const KL = KH + 64 * PK_W;
        uint32_t* const VH = KL + 64 * PK_W;
        uint32_t* const VL = VH + 64 * PK_W;

        // ---- convert pass: split+pack K and V once per CTA ----
        {
            const float* rawK = smem + A_RAW + buf * 2 * KVT_F;
            const float* rawV = rawK + KVT_F;
            // K: [64 keys][16 float4 groups] -> KH/KL[key][d-pair]
            #pragma unroll
            for (int i = 0; i < 4; i++) {
                const int id = tid + (i << 8);
                const int r = id >> 4, c4 = id & 15;
                const float4 kx = *(const float4*)(rawK + r * AP + c4 * 4);
                const float h0 = bf16_hi(kx.x), h1 = bf16_hi(kx.y);
                const float h2 = bf16_hi(kx.z), h3 = bf16_hi(kx.w);
                KH[r * PK_W + 2 * c4]     = pack2_bf16(h0, h1);
                KH[r * PK_W + 2 * c4 + 1] = pack2_bf16(h2, h3);
                KL[r * PK_W + 2 * c4]     = pack2_bf16(kx.x - h0, kx.y - h1);
                KL[r * PK_W + 2 * c4 + 1] = pack2_bf16(kx.z - h2, kx.w - h3);
            }
            // V: pairs of key rows -> VH/VL[d][key-pair] (transposed)
            #pragma unroll
            for (int i = 0; i < 2; i++) {
                const int id = tid + (i << 8);
                const int p = id >> 4, c4 = id & 15;
                const float4 v0 = *(const float4*)(rawV + (2 * p) * AP + c4 * 4);
                const float4 v1 = *(const float4*)(rawV + (2 * p + 1) * AP + c4 * 4);
                const float a0 = bf16_hi(v0.x), b0 = bf16_hi(v1.x);
                const float a1 = bf16_hi(v0.y), b1 = bf16_hi(v1.y);
                const float a2 = bf16_hi(v0.z), b2 = bf16_hi(v1.z);
                const float a3 = bf16_hi(v0.w), b3 = bf16_hi(v1.w);
                VH[(4 * c4 + 0) * PK_W + p] = pack2_bf16(a0, b0);
                VH[(4 * c4 + 1) * PK_W + p] = pack2_bf16(a1, b1);
                VH[(4 * c4 + 2) * PK_W + p] = pack2_bf16(a2, b2);
                VH[(4 * c4 + 3) * PK_W + p] = pack2_bf16(a3, b3);
                VL[(4 * c4 + 0) * PK_W + p] = pack2_bf16(v0.x - a0, v1.x - b0);
                VL[(4 * c4 + 1) * PK_W + p] = pack2_bf16(v0.y - a1, v1.y - b1);
                VL[(4 * c4 + 2) * PK_W + p] = pack2_bf16(v0.z - a2, v1.z - b2);
                VL[(4 * c4 + 3) * PK_W + p] = pack2_bf16(v0.w - a3, v1.w - b3);
            }
        }
        __syncthreads();   // raw[buf] fully consumed; packed[buf] visible

        if (kt + 2 <= ktmax) fill_kv(kt + 2);   // refill freed raw[buf] now

        if (kt == 0) {   // Q fragments: split fp32 -> bf16 hi/lo, pack pairs
            const float* Qp  = smem + (16 * w + g) * AP;
            const float* Qp8 = Qp + 8 * AP;
            #pragma unroll
            for (int kc = 0; kc < 4; kc++) {
                const float2 q0 = *(const float2*)(Qp  + 16 * kc + 2 * tig);
                const float2 q1 = *(const float2*)(Qp8 + 16 * kc + 2 * tig);
                const float2 q2 = *(const float2*)(Qp  + 16 * kc + 2 * tig + 8);
                const float2 q3 = *(const float2*)(Qp8 + 16 * kc + 2 * tig + 8);
                float ha, hb;
                ha = bf16_hi(q0.x); hb = bf16_hi(q0.y);
                Qh[kc][0] = pack2_bf16(ha, hb);
                Ql[kc][0] = pack2_bf16(q0.x - ha, q0.y - hb);
                ha = bf16_hi(q1.x); hb = bf16_hi(q1.y);
                Qh[kc][1] = pack2_bf16(ha, hb);
                Ql[kc][1] = pack2_bf16(q1.x - ha, q1.y - hb);
                ha = bf16_hi(q2.x); hb = bf16_hi(q2.y);
                Qh[kc][2] = pack2_bf16(ha, hb);
                Ql[kc][2] = pack2_bf16(q2.x - ha, q2.y - hb);
                ha = bf16_hi(q3.x); hb = bf16_hi(q3.y);
                Qh[kc][3] = pack2_bf16(ha, hb);
                Ql[kc][3] = pack2_bf16(q3.x - ha, q3.y - hb);
            }
        }

        // ---- S = Q K^T (compensated bf16) ----
        #pragma unroll
        for (int nt = 0; nt < 8; nt++)
            #pragma unroll
            for (int i = 0; i < 4; i++)
                S[nt][i] = 0.0f;

        #pragma unroll
        for (int kc = 0; kc < 4; kc++) {
            #pragma unroll
            for (int nt = 0; nt < 8; nt++) {
                const uint32_t* kh_ = KH + (nt * 8 + g) * PK_W + kc * 8 + tig;
                const uint32_t* kl_ = KL + (nt * 8 + g) * PK_W + kc * 8 + tig;
                uint32_t bh_[2] = { kh_[0], kh_[4] };
                uint32_t bl_[2] = { kl_[0], kl_[4] };
                mma_bf16(S[nt], Qh[kc], bh_);
                mma_bf16(S[nt], Ql[kc], bh_);
                mma_bf16(S[nt], Qh[kc], bl_);
            }
        }

        // ---- causal mask (diagonal region only) ----
        if (kt >= 2 * qt) {
            const int q0 = 16 * w + g;
            const int q1 = q0 + 8;
            const int kb0 = (kt - 2 * qt) * 64;
            #pragma unroll
            for (int nt = 0; nt < 8; nt++) {
                const int kc = kb0 + nt * 8 + 2 * tig;
                if (kc     > q0) S[nt][0] = -1e30f;
                if (kc + 1 > q0) S[nt][1] = -1e30f;
                if (kc     > q1) S[nt][2] = -1e30f;
                if (kc + 1 > q1) S[nt][3] = -1e30f;
            }
        }

        // ---- online softmax (scale 0.125 folded into exp) ----
        float t0 = -1e30f, t1 = -1e30f;
        #pragma unroll
        for (int nt = 0; nt < 8; nt++) {
            t0 = fmaxf(t0, fmaxf(S[nt][0], S[nt][1]));
            t1 = fmaxf(t1, fmaxf(S[nt][2], S[nt][3]));
        }
        #pragma unroll
        for (int o = 1; o <= 2; o <<= 1) {
            t0 = fmaxf(t0, __shfl_xor_sync(0xffffffffu, t0, o));
            t1 = fmaxf(t1, __shfl_xor_sync(0xffffffffu, t1, o));
        }
        const float mn0 = fmaxf(m0, t0), mn1 = fmaxf(m1, t1);
        const float c0 = __expf(0.125f * (m0 - mn0));
        const float c1 = __expf(0.125f * (m1 - mn1));
        m0 = mn0; m1 = mn1;

        float rs0 = 0.0f, rs1 = 0.0f;
        #pragma unroll
        for (int nt = 0; nt < 8; nt++) {
            S[nt][0] = __expf(0.125f * (S[nt][0] - mn0));
            S[nt][1] = __expf(0.125f * (S[nt][1] - mn0));
            S[nt][2] = __expf(0.125f * (S[nt][2] - mn1));
            S[nt][3] = __expf(0.125f * (S[nt][3] - mn1));
            rs0 += S[nt][0] + S[nt][1];
            rs1 += S[nt][2] + S[nt][3];
        }
        #pragma unroll
        for (int o = 1; o <= 2; o <<= 1) {
            rs0 += __shfl_xor_sync(0xffffffffu, rs0, o);
            rs1 += __shfl_xor_sync(0xffffffffu, rs1, o);
        }
        l0 = l0 * c0 + rs0;
        l1 = l1 * c1 + rs1;

        #pragma unroll
        for (int nt = 0; nt < 8; nt++) {
            O[nt][0] *= c0; O[nt][1] *= c0;
            O[nt][2] *= c1; O[nt][3] *= c1;
        }

        // ---- O += P V (compensated bf16; S c-pairs pack directly) ----
        #pragma unroll
        for (int kc = 0; kc < 4; kc++) {
            uint32_t aPh[4], aPl[4];
            {
                float ha, hb;
                ha = bf16_hi(S[2 * kc][0]); hb = bf16_hi(S[2 * kc][1]);
                aPh[0] = pack2_bf16(ha, hb);
                aPl[0] = pack2_bf16(S[2 * kc][0] - ha, S[2 * kc][1] - hb);
                ha = bf16_hi(S[2 * kc][2]); hb = bf16_hi(S[2 * kc][3]);
                aPh[1] = pack2_bf16(ha, hb);
                aPl[1] = pack2_bf16(S[2 * kc][2] - ha, S[2 * kc][3] - hb);
                ha = bf16_hi(S[2 * kc + 1][0]); hb = bf16_hi(S[2 * kc + 1][1]);
                aPh[2] = pack2_bf16(ha, hb);
                aPl[2] = pack2_bf16(S[2 * kc + 1][0] - ha, S[2 * kc + 1][1] - hb);
                ha = bf16_hi(S[2 * kc + 1][2]); hb = bf16_hi(S[2 * kc + 1][3]);
                aPh[3] = pack2_bf16(ha, hb);
                aPl[3] = pack2_bf16(S[2 * kc + 1][2] - ha, S[2 * kc + 1][3] - hb);
            }
            #pragma unroll
            for (int nt = 0; nt < 8; nt++) {
                const uint32_t* vh_ = VH + (nt * 8 + g) * PK_W + kc * 8 + tig;
                const uint32_t* vl_ = VL + (nt * 8 + g) * PK_W + kc * 8 + tig;
                uint32_t bh_[2] = { vh_[0], vh_[4] };
                uint32_t bl_[2] = { vl_[0], vl_[4] };
                mma_bf16(O[nt], aPh, bh_);
                mma_bf16(O[nt], aPl, bh_);
                mma_bf16(O[nt], aPh, bl_);
            }
        }
        // next iteration's top __syncthreads() protects packed[buf] reuse
    }

    // ---- normalize + tf32-round + write ctx (gemm2 reads raw bits) ----
    const float i0 = 1.0f / l0, i1 = 1.0f / l1;
    const size_t row0 = (size_t)b * S_LEN + qt * 128 + 16 * w + g;
    #pragma unroll
    for (int nt = 0; nt < 8; nt++) {
        const int col = h * DH + nt * 8 + 2 * tig;
        float2 o0, o1;
        o0.x = rnd_tf32(O[nt][0] * i0);  o0.y = rnd_tf32(O[nt][1] * i0);
        o1.x = rnd_tf32(O[nt][2] * i1);  o1.y = rnd_tf32(O[nt][3] * i1);
        *(float2*)(ctx + row0 * EMB + col)       = o0;
        *(float2*)(ctx + (row0 + 8) * EMB + col) = o1;
    }
}

// ===========================================================================
// Launch: pre-round -> gemm1 -> attention -> gemm2
// ===========================================================================
extern "C" void kernel_launch(void* const* d_in, const int* in_sizes, int n_in,
                              void* d_out, int out_size)
{
    const float* x     = (const float*)d_in[0];
    const float* w_in  = (const float*)d_in[1];
    const float* b_in  = (const float*)d_in[2];
    const float* w_out = (const float*)d_in[3];
    const float* b_out = (const float*)d_in[4];
    float* out = (float*)d_out;

    float *qkv = nullptr, *ctx = nullptr, *xr = nullptr, *wir = nullptr, *wor = nullptr;
    cudaGetSymbolAddress((void**)&qkv, g_qkv);
    cudaGetSymbolAddress((void**)&ctx, g_ctx);
    cudaGetSymbolAddress((void**)&xr,  g_xr);
    cudaGetSymbolAddress((void**)&wir, g_wir);
    cudaGetSymbolAddress((void**)&wor, g_wor);

    const int M = BATCH * S_LEN;   // 4096

    static bool attr_set = false;
    if (!attr_set) {
        cudaFuncSetAttribute(gemm_mma,
                             cudaFuncAttributeMaxDynamicSharedMemorySize, GM_SMEM);
        cudaFuncSetAttribute(attn_mma_kernel,
                             cudaFuncAttributeMaxDynamicSharedMemorySize, ATT_SMEM);
        attr_set = true;
    }

    // 0) pre-round GEMM operands to tf32 (RNA), once
    {
        const int nx = M * EMB / 4;            // 1048576
        const int nw = 3 * EMB * EMB / 4;      // 786432
        const int no = EMB * EMB / 4;          // 262144
        round_tf32_kernel<<<1184, 256>>>((const float4*)x,     (float4*)xr,  nx);
        round_tf32_kernel<<<1184, 256>>>((const float4*)w_in,  (float4*)wir, nw);
        round_tf32_kernel<<<1184, 256>>>((const float4*)w_out, (float4*)wor, no);
    }

    // 1) qkv = x @ in_proj_w^T + in_proj_b   [4096, 3072]
    gemm_mma<<<dim3((3 * EMB) / 128, M / 128), 256, GM_SMEM>>>(
        xr, wir, b_in, qkv, M, 3 * EMB, EMB);

    // 2) fused causal attention -> ctx [4096, 1024] (tf32-rounded)
    attn_mma_kernel<<<dim3(S_LEN / 128, BATCH * HEADS), 256, ATT_SMEM>>>(qkv, ctx);

    // 3) out = ctx @ out_proj_w^T + out_proj_b   [4096, 1024]
    gemm_mma<<<dim3(EMB / 128, M / 128), 256, GM_SMEM>>>(
        ctx, wor, b_out, out, M, EMB, EMB);
}

// round 11
// speedup vs baseline: 1.0845x; 1.0845x over previous
#include <cuda_runtime.h>
#include <cstdint>

// Problem constants
#define S_LEN 2048
#define EMB   1024
#define HEADS 16
#define DH    64
#define BATCH 2

// Scratch (no allocations allowed)
__device__ float g_qkv[(size_t)BATCH * S_LEN * 3 * EMB];   // [B,S,3E]
__device__ float g_ctx[(size_t)BATCH * S_LEN * EMB];       // [B,S,E] (tf32-rounded)
__device__ float g_xr [(size_t)BATCH * S_LEN * EMB];       // rounded x
__device__ float g_wir[(size_t)3 * EMB * EMB];             // rounded in_proj_w
__device__ float g_wor[(size_t)EMB * EMB];                 // rounded out_proj_w

// ===========================================================================
// Helpers
// ===========================================================================
__device__ __forceinline__ uint32_t smem_u32(const void* p) {
    uint32_t a;
    asm("{ .reg .u64 t; cvta.to.shared.u64 t, %1; cvt.u32.u64 %0, t; }"
        : "=r"(a) : "l"(p));
    return a;
}

__device__ __forceinline__ void cp_async16(uint32_t dst, const void* src) {
    asm volatile("cp.async.cg.shared.global [%0], [%1], 16;"
                 :: "r"(dst), "l"(src));
}
#define CP_COMMIT() asm volatile("cp.async.commit_group;")
#define CP_WAIT1()  asm volatile("cp.async.wait_group 1;")
#define CP_WAIT0()  asm volatile("cp.async.wait_group 0;")

__device__ __forceinline__ uint32_t f2tf32(float f) {
    uint32_t r;
    asm("cvt.rna.tf32.f32 %0, %1;" : "=r"(r) : "f"(f));
    return r;
}
__device__ __forceinline__ float rnd_tf32(float f) {
    return __uint_as_float(f2tf32(f));
}

// Split fp32 into tf32 hi + tf32 lo (3xTF32 error compensation)
__device__ __forceinline__ void tf32_split(float x, uint32_t& hi, uint32_t& lo) {
    hi = f2tf32(x);
    lo = f2tf32(x - __uint_as_float(hi));
}

// mma.sync m16n8k8 tf32: D += A*B, fp32 accumulate
__device__ __forceinline__ void mma_tf32(
    float* c, const uint32_t* a, const uint32_t* b)
{
    asm volatile(
        "mma.sync.aligned.m16n8k8.row.col.f32.tf32.tf32.f32 "
        "{%0,%1,%2,%3}, {%4,%5,%6,%7}, {%8,%9}, {%0,%1,%2,%3};"
        : "+f"(c[0]), "+f"(c[1]), "+f"(c[2]), "+f"(c[3])
        : "r"(a[0]), "r"(a[1]), "r"(a[2]), "r"(a[3]), "r"(b[0]), "r"(b[1]));
}

// ===========================================================================
// Elementwise tf32 pre-rounding (RNA). Idempotent; feeds GEMMs raw bits.
// ===========================================================================
__global__ __launch_bounds__(256) void round_tf32_kernel(
    const float4* __restrict__ src, float4* __restrict__ dst, int n4)
{
    for (int i = blockIdx.x * 256 + threadIdx.x; i < n4; i += gridDim.x * 256) {
        float4 v = src[i];
        v.x = rnd_tf32(v.x); v.y = rnd_tf32(v.y);
        v.z = rnd_tf32(v.z); v.w = rnd_tf32(v.w);
        dst[i] = v;
    }
}

// ===========================================================================
// tf32 tensor-core GEMM on PRE-ROUNDED inputs:
//   C[M,N] = A[M,K] @ B[N,K]^T + bias[N]
// NEW TILING: CTA 256x128, 8 warps as 4(M) x 2(N), warp tile 64x64
// (4 m16 x 8 n8 fragments). Inner loop: 32 LDS / 32 mma (was 24/16),
// raising the issue-bound tensor ceiling ~57% -> ~67%.
// K-chunks of 32, cp.async double-buffered. 1 CTA/SM (108KB smem, ~190 regs).
// ===========================================================================
#define PAD      36
#define AT_ROWS  256
#define BT_ROWS  128
#define A_TILE_F (AT_ROWS * PAD)               // 9216 floats
#define B_TILE_F (BT_ROWS * PAD)               // 4608 floats
#define BUF_F    (A_TILE_F + B_TILE_F)         // 13824 floats per stage
#define GM_SMEM  (2 * BUF_F * 4)               // 110592 bytes

__global__ __launch_bounds__(256) void gemm_mma(
    const float* __restrict__ A, const float* __restrict__ B,
    const float* __restrict__ bias, float* __restrict__ C,
    int M, int N, int K)
{
    extern __shared__ float smem[];
    const int tid  = threadIdx.x;
    const int wid  = tid >> 5;
    const int lane = tid & 31;
    const int wm   = wid >> 1;        // 0..3 -> 64-row band
    const int wn   = wid & 1;         // 0..1 -> 64-col band
    const int g    = lane >> 2;
    const int tig  = lane & 3;
    const int bm   = blockIdx.y * 256;
    const int bn   = blockIdx.x * 128;

    float acc[4][8][4];
    #pragma unroll
    for (int mt = 0; mt < 4; mt++)
        #pragma unroll
        for (int nt = 0; nt < 8; nt++)
            #pragma unroll
            for (int i = 0; i < 4; i++)
                acc[mt][nt][i] = 0.0f;

    auto fill = [&](int buf, int kc) {
        const int k0 = kc << 5;
        const uint32_t sA = smem_u32(smem + buf * BUF_F);
        const uint32_t sB = sA + A_TILE_F * 4;
        // A: 256 rows x 32 k -> 2048 float4, 8 per thread
        #pragma unroll
        for (int i = 0; i < 8; i++) {
            const int id = tid + (i << 8);
            const int r  = id >> 3;
            const int c  = id & 7;
            cp_async16(sA + (uint32_t)(r * PAD + c * 4) * 4,
                       A + (size_t)(bm + r) * K + k0 + c * 4);
        }
        // B: 128 rows x 32 k -> 1024 float4, 4 per thread
        #pragma unroll
        for (int i = 0; i < 4; i++) {
            const int id = tid + (i << 8);
            const int r  = id >> 3;
            const int c  = id & 7;
            cp_async16(sB + (uint32_t)(r * PAD + c * 4) * 4,
                       B + (size_t)(bn + r) * K + k0 + c * 4);
        }
        CP_COMMIT();
    };

    const int NK = K >> 5;
    fill(0, 0);
    fill(1, 1);

    for (int kc = 0; kc < NK; kc++) {
        const int buf = kc & 1;
        if (kc == NK - 1) { CP_WAIT0(); } else { CP_WAIT1(); }
        __syncthreads();

        const float* sA = smem + buf * BUF_F;
        const float* sB = sA + A_TILE_F;

        #pragma unroll
        for (int ks = 0; ks < 4; ks++) {
            const int kb = ks * 8 + tig;
            uint32_t af[4][4], bf[8][2];
            #pragma unroll
            for (int mt = 0; mt < 4; mt++) {
                const float* p = sA + (wm * 64 + mt * 16 + g) * PAD + kb;
                af[mt][0] = __float_as_uint(p[0]);
                af[mt][1] = __float_as_uint(p[8 * PAD]);
                af[mt][2] = __float_as_uint(p[4]);
                af[mt][3] = __float_as_uint(p[8 * PAD + 4]);
            }
            #pragma unroll
            for (int nt = 0; nt < 8; nt++) {
                const float* p = sB + (wn * 64 + nt * 8 + g) * PAD + kb;
                bf[nt][0] = __float_as_uint(p[0]);
                bf[nt][1] = __float_as_uint(p[4]);
            }
            #pragma unroll
            for (int mt = 0; mt < 4; mt++)
                #pragma unroll
                for (int nt = 0; nt < 8; nt++)
                    mma_tf32(acc[mt][nt], af[mt], bf[nt]);
        }
        __syncthreads();

        if (kc + 2 < NK) fill(buf, kc + 2);
    }

    #pragma unroll
    for (int mt = 0; mt < 4; mt++) {
        const int row0 = bm + wm * 64 + mt * 16 + g;
        #pragma unroll
        for (int nt = 0; nt < 8; nt++) {
            const int col = bn + wn * 64 + nt * 8 + 2 * tig;
            const float b0 = bias[col], b1 = bias[col + 1];
            float2 o0, o1;
            o0.x = acc[mt][nt][0] + b0;  o0.y = acc[mt][nt][1] + b1;
            o1.x = acc[mt][nt][2] + b0;  o1.y = acc[mt][nt][3] + b1;
            *(float2*)(C + (size_t)row0 * N + col)       = o0;
            *(float2*)(C + (size_t)(row0 + 8) * N + col) = o1;
        }
    }
}

// ===========================================================================
// Tensor-core flash attention with 3xTF32 error compensation — ROUND-7
// VERSION RESTORED VERBATIM (fastest measured attention: ~415us).
// CTA: 128 queries x one (b,h); 8 warps, 16 q-rows each. Key tiles of 64.
// K/V pre-split into hi/lo tf32 in smem once per CTA per tile; 2-deep raw
// cp.async pipeline; PV A-operand via k-permutation (aP={c0,c2,c1,c3},
// V b-frags from rows {2t,2t+1}).
// ===========================================================================
#define AP        68                            // padded row (floats)
#define QT_F      (128 * AP)                    // 8704 floats
#define KVT_F     (64 * AP)                     // 4352 floats
#define A_KHI     QT_F
#define A_KLO     (QT_F + 2 * KVT_F)
#define A_VHI     (QT_F + 4 * KVT_F)
#define A_VLO     (QT_F + 6 * KVT_F)
#define ATT_SMEM  ((QT_F + 8 * KVT_F) * 4)      // 174080 bytes

__global__ __launch_bounds__(256) void attn_mma_kernel(
    const float* __restrict__ qkv, float* __restrict__ ctx)
{
    extern __shared__ float smem[];
    const int tid  = threadIdx.x;
    const int w    = tid >> 5;
    const int lane = tid & 31;
    const int g    = lane >> 2;
    const int tig  = lane & 3;

    const int qt = gridDim.x - 1 - blockIdx.x;     // heaviest tiles first
    const int bh = blockIdx.y;
    const int b  = bh >> 4;
    const int h  = bh & 15;

    const float* base = qkv + (size_t)b * S_LEN * (3 * EMB);
    const int ktmax = 2 * qt + 1;

    // ---- issue Q stage (group bundled with first KV fill) ----
    {
        const float* Qsrc = base + (size_t)(qt * 128) * (3 * EMB) + h * DH;
        const uint32_t qs = smem_u32(smem);
        #pragma unroll
        for (int i = 0; i < 8; i++) {
            const int id = tid + (i << 8);
            const int r = id >> 4, c4 = id & 15;
            cp_async16(qs + (uint32_t)((r * AP + c4 * 4) * 4),
                       Qsrc + (size_t)r * (3 * EMB) + c4 * 4);
        }
    }

    auto fill_kv = [&](int buf, int kt) {
        const float* Ksrc = base + (size_t)(kt * 64) * (3 * EMB) + EMB + h * DH;
        const float* Vsrc = Ksrc + EMB;
        const uint32_t kd = smem_u32(smem + A_KHI + buf * KVT_F);
        const uint32_t vd = smem_u32(smem + A_VHI + buf * KVT_F);
        #pragma unroll
        for (int i = 0; i < 4; i++) {
            const int id = tid + (i << 8);
            const int r = id >> 4, c4 = id & 15;
            const uint32_t so = (uint32_t)((r * AP + c4 * 4) * 4);
            const size_t go = (size_t)r * (3 * EMB) + c4 * 4;
            cp_async16(kd + so, Ksrc + go);
            cp_async16(vd + so, Vsrc + go);
        }
        CP_COMMIT();
    };

    fill_kv(0, 0);          // group: Q + KV(0)
    fill_kv(1, 1);          // ktmax >= 1 always

    uint32_t Qh[8][4], Ql[8][4];
    float S[8][4];
    float O[8][4];
    float m0 = -1e30f, m1 = -1e30f, l0 = 0.0f, l1 = 0.0f;
    #pragma unroll
    for (int nt = 0; nt < 8; nt++)
        #pragma unroll
        for (int i = 0; i < 4; i++)
            O[nt][i] = 0.0f;

    for (int kt = 0; kt <= ktmax; kt++) {
        if (kt < ktmax) { CP_WAIT1(); } else { CP_WAIT0(); }
        __syncthreads();

        const int buf = kt & 1;

        // ---- convert pass: split this tile's K/V into hi/lo, in place ----
        {
            float* Khi = smem + A_KHI + buf * KVT_F;
            float* Klo = smem + A_KLO + buf * KVT_F;
            float* Vhi = smem + A_VHI + buf * KVT_F;
            float* Vlo = smem + A_VLO + buf * KVT_F;
            #pragma unroll
            for (int i = 0; i < 4; i++) {
                const int id = tid + (i << 8);
                const int off = (id >> 4) * AP + (id & 15) * 4;
                float4 kx = *(float4*)(Khi + off);
                float4 vx = *(float4*)(Vhi + off);
                float4 kh, kl, vh, vl;
                kh.x = rnd_tf32(kx.x); kl.x = rnd_tf32(kx.x - kh.x);
                kh.y = rnd_tf32(kx.y); kl.y = rnd_tf32(kx.y - kh.y);
                kh.z = rnd_tf32(kx.z); kl.z = rnd_tf32(kx.z - kh.z);
                kh.w = rnd_tf32(kx.w); kl.w = rnd_tf32(kx.w - kh.w);
                vh.x = rnd_tf32(vx.x); vl.x = rnd_tf32(vx.x - vh.x);
                vh.y = rnd_tf32(vx.y); vl.y = rnd_tf32(vx.y - vh.y);
                vh.z = rnd_tf32(vx.z); vl.z = rnd_tf32(vx.z - vh.z);
                vh.w = rnd_tf32(vx.w); vl.w = rnd_tf32(vx.w - vh.w);
                *(float4*)(Khi + off) = kh;  *(float4*)(Klo + off) = kl;
                *(float4*)(Vhi + off) = vh;  *(float4*)(Vlo + off) = vl;
            }
        }
        __syncthreads();

        if (kt == 0) {   // Q fragments, split into tf32 hi/lo once
            const float* Qp = smem + (16 * w + g) * AP + tig;
            #pragma unroll
            for (int kb = 0; kb < 8; kb++) {
                tf32_split(Qp[kb * 8],              Qh[kb][0], Ql[kb][0]);
                tf32_split(Qp[8 * AP + kb * 8],     Qh[kb][1], Ql[kb][1]);
                tf32_split(Qp[kb * 8 + 4],          Qh[kb][2], Ql[kb][2]);
                tf32_split(Qp[8 * AP + kb * 8 + 4], Qh[kb][3], Ql[kb][3]);
            }
        }

        const float* Khl = smem + A_KHI + buf * KVT_F + g * AP + tig;
        const float* Kll = smem + A_KLO + buf * KVT_F + g * AP + tig;
        const float* Vhl = smem + A_VHI + buf * KVT_F + 2 * tig * AP + g;
        const float* Vll = smem + A_VLO + buf * KVT_F + 2 * tig * AP + g;

        // ---- S = Q K^T (3xTF32) ----
        #pragma unroll
        for (int nt = 0; nt < 8; nt++)
            #pragma unroll
            for (int i = 0; i < 4; i++)
                S[nt][i] = 0.0f;

        #pragma unroll
        for (int kb = 0; kb < 8; kb++) {
            #pragma unroll
            for (int nt = 0; nt < 8; nt++) {
                const int so = nt * (8 * AP) + kb * 8;
                uint32_t bh_[2], bl_[2];
                bh_[0] = __float_as_uint(Khl[so]);
                bh_[1] = __float_as_uint(Khl[so + 4]);
                bl_[0] = __float_as_uint(Kll[so]);
                bl_[1] = __float_as_uint(Kll[so + 4]);
                mma_tf32(S[nt], Qh[kb], bh_);
                mma_tf32(S[nt], Qh[kb], bl_);
                mma_tf32(S[nt], Ql[kb], bh_);
            }
        }

        // ---- causal mask (diagonal region only) ----
        if (kt >= 2 * qt) {
            const int q0 = 16 * w + g;
            const int q1 = q0 + 8;
            const int kb0 = (kt - 2 * qt) * 64;
            #pragma unroll
            for (int nt = 0; nt < 8; nt++) {
                const int kc = kb0 + nt * 8 + 2 * tig;
                if (kc     > q0) S[nt][0] = -1e30f;
                if (kc + 1 > q0) S[nt][1] = -1e30f;
                if (kc     > q1) S[nt][2] = -1e30f;
                if (kc + 1 > q1) S[nt][3] = -1e30f;
            }
        }

        // ---- online softmax (scale 0.125 folded into exp) ----
        float t0 = -1e30f, t1 = -1e30f;
        #pragma unroll
        for (int nt = 0; nt < 8; nt++) {
            t0 = fmaxf(t0, fmaxf(S[nt][0], S[nt][1]));
            t1 = fmaxf(t1, fmaxf(S[nt][2], S[nt][3]));
        }
        #pragma unroll
        for (int o = 1; o <= 2; o <<= 1) {
            t0 = fmaxf(t0, __shfl_xor_sync(0xffffffffu, t0, o));
            t1 = fmaxf(t1, __shfl_xor_sync(0xffffffffu, t1, o));
        }
        const float mn0 = fmaxf(m0, t0), mn1 = fmaxf(m1, t1);
        const float c0 = __expf(0.125f * (m0 - mn0));
        const float c1 = __expf(0.125f * (m1 - mn1));
        m0 = mn0; m1 = mn1;

        float rs0 = 0.0f, rs1 = 0.0f;
        #pragma unroll
        for (int nt = 0; nt < 8; nt++) {
            S[nt][0] = __expf(0.125f * (S[nt][0] - mn0));
            S[nt][1] = __expf(0.125f * (S[nt][1] - mn0));
            S[nt][2] = __expf(0.125f * (S[nt][2] - mn1));
            S[nt][3] = __expf(0.125f * (S[nt][3] - mn1));
            rs0 += S[nt][0] + S[nt][1];
            rs1 += S[nt][2] + S[nt][3];
        }
        #pragma unroll
        for (int o = 1; o <= 2; o <<= 1) {
            rs0 += __shfl_xor_sync(0xffffffffu, rs0, o);
            rs1 += __shfl_xor_sync(0xffffffffu, rs1, o);
        }
        l0 = l0 * c0 + rs0;
        l1 = l1 * c1 + rs1;

        #pragma unroll
        for (int nt = 0; nt < 8; nt++) {
            O[nt][0] *= c0; O[nt][1] *= c0;
            O[nt][2] *= c1; O[nt][3] *= c1;
        }

        // ---- O += P V (3-term compensated; k-permuted layout) ----
        #pragma unroll
        for (int kb = 0; kb < 8; kb++) {
            uint32_t aPh[4], aPl[4];
            tf32_split(S[kb][0], aPh[0], aPl[0]);
            tf32_split(S[kb][2], aPh[1], aPl[1]);
            tf32_split(S[kb][1], aPh[2], aPl[2]);
            tf32_split(S[kb][3], aPh[3], aPl[3]);
            #pragma unroll
            for (int nt = 0; nt < 8; nt++) {
                const int so = kb * (8 * AP) + nt * 8;
                uint32_t bh_[2], bl_[2];
                bh_[0] = __float_as_uint(Vhl[so]);
                bh_[1] = __float_as_uint(Vhl[so + AP]);
                bl_[0] = __float_as_uint(Vll[so]);
                bl_[1] = __float_as_uint(Vll[so + AP]);
                mma_tf32(O[nt], aPh, bh_);
                mma_tf32(O[nt], aPl, bh_);
                mma_tf32(O[nt], aPh, bl_);
            }
        }

        __syncthreads();   // all readers done before refill of this buffer
        if (kt + 2 <= ktmax) fill_kv(buf, kt + 2);
    }

    // ---- normalize + tf32-round + write ctx (gemm2 reads raw bits) ----
    const float i0 = 1.0f / l0, i1 = 1.0f / l1;
    const size_t row0 = (size_t)b * S_LEN + qt * 128 + 16 * w + g;
    #pragma unroll
    for (int nt = 0; nt < 8; nt++) {
        const int col = h * DH + nt * 8 + 2 * tig;
        float2 o0, o1;
        o0.x = rnd_tf32(O[nt][0] * i0);  o0.y = rnd_tf32(O[nt][1] * i0);
        o1.x = rnd_tf32(O[nt][2] * i1);  o1.y = rnd_tf32(O[nt][3] * i1);
        *(float2*)(ctx + row0 * EMB + col)       = o0;
        *(float2*)(ctx + (row0 + 8) * EMB + col) = o1;
    }
}

// ===========================================================================
// Launch: pre-round -> gemm1 -> attention -> gemm2
// ===========================================================================
extern "C" void kernel_launch(void* const* d_in, const int* in_sizes, int n_in,
                              void* d_out, int out_size)
{
    const float* x     = (const float*)d_in[0];
    const float* w_in  = (const float*)d_in[1];
    const float* b_in  = (const float*)d_in[2];
    const float* w_out = (const float*)d_in[3];
    const float* b_out = (const float*)d_in[4];
    float* out = (float*)d_out;

    float *qkv = nullptr, *ctx = nullptr, *xr = nullptr, *wir = nullptr, *wor = nullptr;
    cudaGetSymbolAddress((void**)&qkv, g_qkv);
    cudaGetSymbolAddress((void**)&ctx, g_ctx);
    cudaGetSymbolAddress((void**)&xr,  g_xr);
    cudaGetSymbolAddress((void**)&wir, g_wir);
    cudaGetSymbolAddress((void**)&wor, g_wor);

    const int M = BATCH * S_LEN;   // 4096

    static bool attr_set = false;
    if (!attr_set) {
        cudaFuncSetAttribute(gemm_mma,
                             cudaFuncAttributeMaxDynamicSharedMemorySize, GM_SMEM);
        cudaFuncSetAttribute(attn_mma_kernel,
                             cudaFuncAttributeMaxDynamicSharedMemorySize, ATT_SMEM);
        attr_set = true;
    }

    // 0) pre-round GEMM operands to tf32 (RNA), once
    {
        const int nx = M * EMB / 4;            // 1048576
        const int nw = 3 * EMB * EMB / 4;      // 786432
        const int no = EMB * EMB / 4;          // 262144
        round_tf32_kernel<<<1184, 256>>>((const float4*)x,     (float4*)xr,  nx);
        round_tf32_kernel<<<1184, 256>>>((const float4*)w_in,  (float4*)wir, nw);
        round_tf32_kernel<<<1184, 256>>>((const float4*)w_out, (float4*)wor, no);
    }

    // 1) qkv = x @ in_proj_w^T + in_proj_b   [4096, 3072]
    gemm_mma<<<dim3((3 * EMB) / 128, M / 256), 256, GM_SMEM>>>(
        xr, wir, b_in, qkv, M, 3 * EMB, EMB);

    // 2) fused causal attention -> ctx [4096, 1024] (tf32-rounded)
    attn_mma_kernel<<<dim3(S_LEN / 128, BATCH * HEADS), 256, ATT_SMEM>>>(qkv, ctx);

    // 3) out = ctx @ out_proj_w^T + out_proj_b   [4096, 1024]
    gemm_mma<<<dim3(EMB / 128, M / 256), 256, GM_SMEM>>>(
        ctx, wor, b_out, out, M, EMB, EMB);
}

// round 12
// speedup vs baseline: 1.1288x; 1.0408x over previous
#include <cuda_runtime.h>
#include <cstdint>

// Problem constants
#define S_LEN 2048
#define EMB   1024
#define HEADS 16
#define DH    64
#define BATCH 2

// Scratch (no allocations allowed)
__device__ float g_q  [(size_t)BATCH * S_LEN * EMB];   // Q (fp32)
__device__ float g_khi[(size_t)BATCH * S_LEN * EMB];   // K tf32 hi
__device__ float g_klo[(size_t)BATCH * S_LEN * EMB];   // K tf32 lo
__device__ float g_vhi[(size_t)BATCH * S_LEN * EMB];   // V tf32 hi
__device__ float g_vlo[(size_t)BATCH * S_LEN * EMB];   // V tf32 lo
__device__ float g_ctx[(size_t)BATCH * S_LEN * EMB];   // attention out (tf32-rounded)
__device__ float g_xr [(size_t)BATCH * S_LEN * EMB];   // rounded x
__device__ float g_wir[(size_t)3 * EMB * EMB];         // rounded in_proj_w
__device__ float g_wor[(size_t)EMB * EMB];             // rounded out_proj_w

// ===========================================================================
// Helpers
// ===========================================================================
__device__ __forceinline__ uint32_t smem_u32(const void* p) {
    uint32_t a;
    asm("{ .reg .u64 t; cvta.to.shared.u64 t, %1; cvt.u32.u64 %0, t; }"
        : "=r"(a) : "l"(p));
    return a;
}

__device__ __forceinline__ void cp_async16(uint32_t dst, const void* src) {
    asm volatile("cp.async.cg.shared.global [%0], [%1], 16;"
                 :: "r"(dst), "l"(src));
}
#define CP_COMMIT() asm volatile("cp.async.commit_group;")
#define CP_WAIT1()  asm volatile("cp.async.wait_group 1;")
#define CP_WAIT0()  asm volatile("cp.async.wait_group 0;")

__device__ __forceinline__ uint32_t f2tf32(float f) {
    uint32_t r;
    asm("cvt.rna.tf32.f32 %0, %1;" : "=r"(r) : "f"(f));
    return r;
}
__device__ __forceinline__ float rnd_tf32(float f) {
    return __uint_as_float(f2tf32(f));
}

// Split fp32 into tf32 hi + tf32 lo (3xTF32 error compensation)
__device__ __forceinline__ void tf32_split(float x, uint32_t& hi, uint32_t& lo) {
    hi = f2tf32(x);
    lo = f2tf32(x - __uint_as_float(hi));
}
__device__ __forceinline__ void tf32_split_f(float x, float& hi, float& lo) {
    uint32_t h, l;
    tf32_split(x, h, l);
    hi = __uint_as_float(h);
    lo = __uint_as_float(l);
}

// mma.sync m16n8k8 tf32: D += A*B, fp32 accumulate
__device__ __forceinline__ void mma_tf32(
    float* c, const uint32_t* a, const uint32_t* b)
{
    asm volatile(
        "mma.sync.aligned.m16n8k8.row.col.f32.tf32.tf32.f32 "
        "{%0,%1,%2,%3}, {%4,%5,%6,%7}, {%8,%9}, {%0,%1,%2,%3};"
        : "+f"(c[0]), "+f"(c[1]), "+f"(c[2]), "+f"(c[3])
        : "r"(a[0]), "r"(a[1]), "r"(a[2]), "r"(a[3]), "r"(b[0]), "r"(b[1]));
}

// ===========================================================================
// Elementwise tf32 pre-rounding (RNA). Idempotent; feeds GEMMs raw bits.
// ===========================================================================
__global__ __launch_bounds__(256) void round_tf32_kernel(
    const float4* __restrict__ src, float4* __restrict__ dst, int n4)
{
    for (int i = blockIdx.x * 256 + threadIdx.x; i < n4; i += gridDim.x * 256) {
        float4 v = src[i];
        v.x = rnd_tf32(v.x); v.y = rnd_tf32(v.y);
        v.z = rnd_tf32(v.z); v.w = rnd_tf32(v.w);
        dst[i] = v;
    }
}

// ===========================================================================
// tf32 tensor-core GEMM on PRE-ROUNDED inputs:
//   C[M,N] = A[M,K] @ B[N,K]^T + bias[N]
// CTA 256x128, 8 warps as 4(M) x 2(N), warp tile 64x64.
// SPLIT MODE (qkv != nullptr): the N=3072 output is routed per 1024-column
// region: Q -> gq (plain), K -> gkhi/gklo (tf32 hi/lo), V -> gvhi/gvlo.
// This hoists the attention kernel's per-tile K/V convert pass into the
// GEMM epilogue, done ONCE instead of ~16x per tile.
// ===========================================================================
#define PAD      36
#define A_TILE_F (256 * PAD)
#define B_TILE_F (128 * PAD)
#define BUF_F    (A_TILE_F + B_TILE_F)
#define GM_SMEM  (2 * BUF_F * 4)               // 110592 bytes

__global__ __launch_bounds__(256) void gemm_mma(
    const float* __restrict__ A, const float* __restrict__ B,
    const float* __restrict__ bias, float* __restrict__ C,
    int M, int N, int K,
    float* __restrict__ gq,
    float* __restrict__ gkhi, float* __restrict__ gklo,
    float* __restrict__ gvhi, float* __restrict__ gvlo)
{
    extern __shared__ float smem[];
    const int tid  = threadIdx.x;
    const int wid  = tid >> 5;
    const int lane = tid & 31;
    const int wm   = wid >> 1;
    const int wn   = wid & 1;
    const int g    = lane >> 2;
    const int tig  = lane & 3;
    const int bm   = blockIdx.y * 256;
    const int bn   = blockIdx.x * 128;

    float acc[4][8][4];
    #pragma unroll
    for (int mt = 0; mt < 4; mt++)
        #pragma unroll
        for (int nt = 0; nt < 8; nt++)
            #pragma unroll
            for (int i = 0; i < 4; i++)
                acc[mt][nt][i] = 0.0f;

    auto fill = [&](int buf, int kc) {
        const int k0 = kc << 5;
        const uint32_t sA = smem_u32(smem + buf * BUF_F);
        const uint32_t sB = sA + A_TILE_F * 4;
        #pragma unroll
        for (int i = 0; i < 8; i++) {
            const int id = tid + (i << 8);
            const int r  = id >> 3;
            const int c  = id & 7;
            cp_async16(sA + (uint32_t)(r * PAD + c * 4) * 4,
                       A + (size_t)(bm + r) * K + k0 + c * 4);
        }
        #pragma unroll
        for (int i = 0; i < 4; i++) {
            const int id = tid + (i << 8);
            const int r  = id >> 3;
            const int c  = id & 7;
            cp_async16(sB + (uint32_t)(r * PAD + c * 4) * 4,
                       B + (size_t)(bn + r) * K + k0 + c * 4);
        }
        CP_COMMIT();
    };

    const int NK = K >> 5;
    fill(0, 0);
    fill(1, 1);

    for (int kc = 0; kc < NK; kc++) {
        const int buf = kc & 1;
        if (kc == NK - 1) { CP_WAIT0(); } else { CP_WAIT1(); }
        __syncthreads();

        const float* sA = smem + buf * BUF_F;
        const float* sB = sA + A_TILE_F;

        #pragma unroll
        for (int ks = 0; ks < 4; ks++) {
            const int kb = ks * 8 + tig;
            uint32_t af[4][4], bf[8][2];
            #pragma unroll
            for (int mt = 0; mt < 4; mt++) {
                const float* p = sA + (wm * 64 + mt * 16 + g) * PAD + kb;
                af[mt][0] = __float_as_uint(p[0]);
                af[mt][1] = __float_as_uint(p[8 * PAD]);
                af[mt][2] = __float_as_uint(p[4]);
                af[mt][3] = __float_as_uint(p[8 * PAD + 4]);
            }
            #pragma unroll
            for (int nt = 0; nt < 8; nt++) {
                const float* p = sB + (wn * 64 + nt * 8 + g) * PAD + kb;
                bf[nt][0] = __float_as_uint(p[0]);
                bf[nt][1] = __float_as_uint(p[4]);
            }
            #pragma unroll
            for (int mt = 0; mt < 4; mt++)
                #pragma unroll
                for (int nt = 0; nt < 8; nt++)
                    mma_tf32(acc[mt][nt], af[mt], bf[nt]);
        }
        __syncthreads();

        if (kc + 2 < NK) fill(buf, kc + 2);
    }

    // ---- epilogue ----
    const int region = (gq != nullptr) ? (bn >> 10) : -1;   // 0=Q, 1=K, 2=V
    #pragma unroll
    for (int mt = 0; mt < 4; mt++) {
        const int row0 = bm + wm * 64 + mt * 16 + g;
        #pragma unroll
        for (int nt = 0; nt < 8; nt++) {
            const int col = bn + wn * 64 + nt * 8 + 2 * tig;
            const float b0 = bias[col], b1 = bias[col + 1];
            float2 o0, o1;
            o0.x = acc[mt][nt][0] + b0;  o0.y = acc[mt][nt][1] + b1;
            o1.x = acc[mt][nt][2] + b0;  o1.y = acc[mt][nt][3] + b1;

            if (region < 0) {
                *(float2*)(C + (size_t)row0 * N + col)       = o0;
                *(float2*)(C + (size_t)(row0 + 8) * N + col) = o1;
            } else {
                const int lcol = col & 1023;
                const size_t i0 = (size_t)row0 * EMB + lcol;
                const size_t i1 = (size_t)(row0 + 8) * EMB + lcol;
                if (region == 0) {
                    *(float2*)(gq + i0) = o0;
                    *(float2*)(gq + i1) = o1;
                } else {
                    float2 h0, l0, h1, l1;
                    tf32_split_f(o0.x, h0.x, l0.x);
                    tf32_split_f(o0.y, h0.y, l0.y);
                    tf32_split_f(o1.x, h1.x, l1.x);
                    tf32_split_f(o1.y, h1.y, l1.y);
                    float* hi_dst = (region == 1) ? gkhi : gvhi;
                    float* lo_dst = (region == 1) ? gklo : gvlo;
                    *(float2*)(hi_dst + i0) = h0;
                    *(float2*)(lo_dst + i0) = l0;
                    *(float2*)(hi_dst + i1) = h1;
                    *(float2*)(lo_dst + i1) = l1;
                }
            }
        }
    }
}

// ===========================================================================
// Tensor-core flash attention, 3xTF32 compensated, PRE-SPLIT K/V from global.
// CTA: 128 queries x one (b,h); 8 warps, 16 q-rows each. Key tiles of 64.
// K/V hi/lo are produced once by gemm1's epilogue; fill_kv streams all four
// (Khi,Klo,Vhi,Vlo) directly into the smem slots the old convert pass filled.
// The per-tile convert pass and one __syncthreads are GONE; mainloop math,
// layout, and numerics are bit-identical to round 7/11.
// ===========================================================================
#define AP        68                            // padded row (floats)
#define QT_F      (128 * AP)                    // 8704 floats
#define KVT_F     (64 * AP)                     // 4352 floats
#define A_KHI     QT_F
#define A_KLO     (QT_F + 2 * KVT_F)
#define A_VHI     (QT_F + 4 * KVT_F)
#define A_VLO     (QT_F + 6 * KVT_F)
#define ATT_SMEM  ((QT_F + 8 * KVT_F) * 4)      // 174080 bytes

__global__ __launch_bounds__(256) void attn_mma_kernel(
    const float* __restrict__ gq,
    const float* __restrict__ gkhi, const float* __restrict__ gklo,
    const float* __restrict__ gvhi, const float* __restrict__ gvlo,
    float* __restrict__ ctx)
{
    extern __shared__ float smem[];
    const int tid  = threadIdx.x;
    const int w    = tid >> 5;
    const int lane = tid & 31;
    const int g    = lane >> 2;
    const int tig  = lane & 3;

    const int qt = gridDim.x - 1 - blockIdx.x;     // heaviest tiles first
    const int bh = blockIdx.y;
    const int b  = bh >> 4;
    const int h  = bh & 15;

    const size_t bbase = (size_t)b * S_LEN * EMB + h * DH;
    const int ktmax = 2 * qt + 1;

    // ---- issue Q stage (group bundled with first KV fill) ----
    {
        const float* Qsrc = gq + bbase + (size_t)(qt * 128) * EMB;
        const uint32_t qs = smem_u32(smem);
        #pragma unroll
        for (int i = 0; i < 8; i++) {
            const int id = tid + (i << 8);
            const int r = id >> 4, c4 = id & 15;
            cp_async16(qs + (uint32_t)((r * AP + c4 * 4) * 4),
                       Qsrc + (size_t)r * EMB + c4 * 4);
        }
    }

    auto fill_kv = [&](int buf, int kt) {
        const size_t tbase = bbase + (size_t)(kt * 64) * EMB;
        const uint32_t kh = smem_u32(smem + A_KHI + buf * KVT_F);
        const uint32_t kl = smem_u32(smem + A_KLO + buf * KVT_F);
        const uint32_t vh = smem_u32(smem + A_VHI + buf * KVT_F);
        const uint32_t vl = smem_u32(smem + A_VLO + buf * KVT_F);
        #pragma unroll
        for (int i = 0; i < 4; i++) {
            const int id = tid + (i << 8);
            const int r = id >> 4, c4 = id & 15;
            const uint32_t so = (uint32_t)((r * AP + c4 * 4) * 4);
            const size_t go = tbase + (size_t)r * EMB + c4 * 4;
            cp_async16(kh + so, gkhi + go);
            cp_async16(kl + so, gklo + go);
            cp_async16(vh + so, gvhi + go);
            cp_async16(vl + so, gvlo + go);
        }
        CP_COMMIT();
    };

    fill_kv(0, 0);          // group: Q + KV(0)
    fill_kv(1, 1);          // ktmax >= 1 always

    uint32_t Qh[8][4], Ql[8][4];
    float S[8][4];
    float O[8][4];
    float m0 = -1e30f, m1 = -1e30f, l0 = 0.0f, l1 = 0.0f;
    #pragma unroll
    for (int nt = 0; nt < 8; nt++)
        #pragma unroll
        for (int i = 0; i < 4; i++)
            O[nt][i] = 0.0f;

    for (int kt = 0; kt <= ktmax; kt++) {
        if (kt < ktmax) { CP_WAIT1(); } else { CP_WAIT0(); }
        __syncthreads();

        const int buf = kt & 1;

        if (kt == 0) {   // Q fragments, split into tf32 hi/lo once
            const float* Qp = smem + (16 * w + g) * AP + tig;
            #pragma unroll
            for (int kb = 0; kb < 8; kb++) {
                tf32_split(Qp[kb * 8],              Qh[kb][0], Ql[kb][0]);
                tf32_split(Qp[8 * AP + kb * 8],     Qh[kb][1], Ql[kb][1]);
                tf32_split(Qp[kb * 8 + 4],          Qh[kb][2], Ql[kb][2]);
                tf32_split(Qp[8 * AP + kb * 8 + 4], Qh[kb][3], Ql[kb][3]);
            }
        }

        const float* Khl = smem + A_KHI + buf * KVT_F + g * AP + tig;
        const float* Kll = smem + A_KLO + buf * KVT_F + g * AP + tig;
        const float* Vhl = smem + A_VHI + buf * KVT_F + 2 * tig * AP + g;
        const float* Vll = smem + A_VLO + buf * KVT_F + 2 * tig * AP + g;

        // ---- S = Q K^T (3xTF32) ----
        #pragma unroll
        for (int nt = 0; nt < 8; nt++)
            #pragma unroll
            for (int i = 0; i < 4; i++)
                S[nt][i] = 0.0f;

        #pragma unroll
        for (int kb = 0; kb < 8; kb++) {
            #pragma unroll
            for (int nt = 0; nt < 8; nt++) {
                const int so = nt * (8 * AP) + kb * 8;
                uint32_t bh_[2], bl_[2];
                bh_[0] = __float_as_uint(Khl[so]);
                bh_[1] = __float_as_uint(Khl[so + 4]);
                bl_[0] = __float_as_uint(Kll[so]);
                bl_[1] = __float_as_uint(Kll[so + 4]);
                mma_tf32(S[nt], Qh[kb], bh_);
                mma_tf32(S[nt], Qh[kb], bl_);
                mma_tf32(S[nt], Ql[kb], bh_);
            }
        }

        // ---- causal mask (diagonal region only) ----
        if (kt >= 2 * qt) {
            const int q0 = 16 * w + g;
            const int q1 = q0 + 8;
            const int kb0 = (kt - 2 * qt) * 64;
            #pragma unroll
            for (int nt = 0; nt < 8; nt++) {
                const int kc = kb0 + nt * 8 + 2 * tig;
                if (kc     > q0) S[nt][0] = -1e30f;
                if (kc + 1 > q0) S[nt][1] = -1e30f;
                if (kc     > q1) S[nt][2] = -1e30f;
                if (kc + 1 > q1) S[nt][3] = -1e30f;
            }
        }

        // ---- online softmax (scale 0.125 folded into exp) ----
        float t0 = -1e30f, t1 = -1e30f;
        #pragma unroll
        for (int nt = 0; nt < 8; nt++) {
            t0 = fmaxf(t0, fmaxf(S[nt][0], S[nt][1]));
            t1 = fmaxf(t1, fmaxf(S[nt][2], S[nt][3]));
        }
        #pragma unroll
        for (int o = 1; o <= 2; o <<= 1) {
            t0 = fmaxf(t0, __shfl_xor_sync(0xffffffffu, t0, o));
            t1 = fmaxf(t1, __shfl_xor_sync(0xffffffffu, t1, o));
        }
        const float mn0 = fmaxf(m0, t0), mn1 = fmaxf(m1, t1);
        const float c0 = __expf(0.125f * (m0 - mn0));
        const float c1 = __expf(0.125f * (m1 - mn1));
        m0 = mn0; m1 = mn1;

        float rs0 = 0.0f, rs1 = 0.0f;
        #pragma unroll
        for (int nt = 0; nt < 8; nt++) {
            S[nt][0] = __expf(0.125f * (S[nt][0] - mn0));
            S[nt][1] = __expf(0.125f * (S[nt][1] - mn0));
            S[nt][2] = __expf(0.125f * (S[nt][2] - mn1));
            S[nt][3] = __expf(0.125f * (S[nt][3] - mn1));
            rs0 += S[nt][0] + S[nt][1];
            rs1 += S[nt][2] + S[nt][3];
        }
        #pragma unroll
        for (int o = 1; o <= 2; o <<= 1) {
            rs0 += __shfl_xor_sync(0xffffffffu, rs0, o);
            rs1 += __shfl_xor_sync(0xffffffffu, rs1, o);
        }
        l0 = l0 * c0 + rs0;
        l1 = l1 * c1 + rs1;

        #pragma unroll
        for (int nt = 0; nt < 8; nt++) {
            O[nt][0] *= c0; O[nt][1] *= c0;
            O[nt][2] *= c1; O[nt][3] *= c1;
        }

        // ---- O += P V (3-term compensated; k-permuted layout) ----
        #pragma unroll
        for (int kb = 0; kb < 8; kb++) {
            uint32_t aPh[4], aPl[4];
            tf32_split(S[kb][0], aPh[0], aPl[0]);
            tf32_split(S[kb][2], aPh[1], aPl[1]);
            tf32_split(S[kb][1], aPh[2], aPl[2]);
            tf32_split(S[kb][3], aPh[3], aPl[3]);
            #pragma unroll
            for (int nt = 0; nt < 8; nt++) {
                const int so = kb * (8 * AP) + nt * 8;
                uint32_t bh_[2], bl_[2];
                bh_[0] = __float_as_uint(Vhl[so]);
                bh_[1] = __float_as_uint(Vhl[so + AP]);
                bl_[0] = __float_as_uint(Vll[so]);
                bl_[1] = __float_as_uint(Vll[so + AP]);
                mma_tf32(O[nt], aPh, bh_);
                mma_tf32(O[nt], aPl, bh_);
                mma_tf32(O[nt], aPh, bl_);
            }
        }

        __syncthreads();   // all readers done before refill of this buffer
        if (kt + 2 <= ktmax) fill_kv(buf, kt + 2);
    }

    // ---- normalize + tf32-round + write ctx (gemm2 reads raw bits) ----
    const float i0 = 1.0f / l0, i1 = 1.0f / l1;
    const size_t row0 = (size_t)b * S_LEN + qt * 128 + 16 * w + g;
    #pragma unroll
    for (int nt = 0; nt < 8; nt++) {
        const int col = h * DH + nt * 8 + 2 * tig;
        float2 o0, o1;
        o0.x = rnd_tf32(O[nt][0] * i0);  o0.y = rnd_tf32(O[nt][1] * i0);
        o1.x = rnd_tf32(O[nt][2] * i1);  o1.y = rnd_tf32(O[nt][3] * i1);
        *(float2*)(ctx + row0 * EMB + col)       = o0;
        *(float2*)(ctx + (row0 + 8) * EMB + col) = o1;
    }
}

// ===========================================================================
// Launch: pre-round -> gemm1 (split epilogue) -> attention -> gemm2
// ===========================================================================
extern "C" void kernel_launch(void* const* d_in, const int* in_sizes, int n_in,
                              void* d_out, int out_size)
{
    const float* x     = (const float*)d_in[0];
    const float* w_in  = (const float*)d_in[1];
    const float* b_in  = (const float*)d_in[2];
    const float* w_out = (const float*)d_in[3];
    const float* b_out = (const float*)d_in[4];
    float* out = (float*)d_out;

    float *gq, *gkhi, *gklo, *gvhi, *gvlo, *ctx, *xr, *wir, *wor;
    cudaGetSymbolAddress((void**)&gq,   g_q);
    cudaGetSymbolAddress((void**)&gkhi, g_khi);
    cudaGetSymbolAddress((void**)&gklo, g_klo);
    cudaGetSymbolAddress((void**)&gvhi, g_vhi);
    cudaGetSymbolAddress((void**)&gvlo, g_vlo);
    cudaGetSymbolAddress((void**)&ctx,  g_ctx);
    cudaGetSymbolAddress((void**)&xr,   g_xr);
    cudaGetSymbolAddress((void**)&wir,  g_wir);
    cudaGetSymbolAddress((void**)&wor,  g_wor);

    const int M = BATCH * S_LEN;   // 4096

    static bool attr_set = false;
    if (!attr_set) {
        cudaFuncSetAttribute(gemm_mma,
                             cudaFuncAttributeMaxDynamicSharedMemorySize, GM_SMEM);
        cudaFuncSetAttribute(attn_mma_kernel,
                             cudaFuncAttributeMaxDynamicSharedMemorySize, ATT_SMEM);
        attr_set = true;
    }

    // 0) pre-round GEMM operands to tf32 (RNA), once
    {
        const int nx = M * EMB / 4;            // 1048576
        const int nw = 3 * EMB * EMB / 4;      // 786432
        const int no = EMB * EMB / 4;          // 262144
        round_tf32_kernel<<<1184, 256>>>((const float4*)x,     (float4*)xr,  nx);
        round_tf32_kernel<<<1184, 256>>>((const float4*)w_in,  (float4*)wir, nw);
        round_tf32_kernel<<<1184, 256>>>((const float4*)w_out, (float4*)wor, no);
    }

    // 1) qkv projection with split epilogue: Q plain, K/V tf32 hi+lo
    gemm_mma<<<dim3((3 * EMB) / 128, M / 256), 256, GM_SMEM>>>(
        xr, wir, b_in, nullptr, M, 3 * EMB, EMB,
        gq, gkhi, gklo, gvhi, gvlo);

    // 2) fused causal attention -> ctx [4096, 1024] (tf32-rounded)
    attn_mma_kernel<<<dim3(S_LEN / 128, BATCH * HEADS), 256, ATT_SMEM>>>(
        gq, gkhi, gklo, gvhi, gvlo, ctx);

    // 3) out = ctx @ out_proj_w^T + out_proj_b   [4096, 1024]
    gemm_mma<<<dim3(EMB / 128, M / 256), 256, GM_SMEM>>>(
        ctx, wor, b_out, out, M, EMB, EMB,
        nullptr, nullptr, nullptr, nullptr, nullptr);
}

// round 13
// speedup vs baseline: 1.1418x; 1.0116x over previous
#include <cuda_runtime.h>
#include <cstdint>

// Problem constants
#define S_LEN 2048
#define EMB   1024
#define HEADS 16
#define DH    64
#define BATCH 2

// Scratch (no allocations allowed)
__device__ float g_q  [(size_t)BATCH * S_LEN * EMB];   // Q (fp32)
__device__ float g_khi[(size_t)BATCH * S_LEN * EMB];   // K tf32 hi
__device__ float g_klo[(size_t)BATCH * S_LEN * EMB];   // K tf32 lo
__device__ float g_vhi[(size_t)BATCH * S_LEN * EMB];   // V tf32 hi
__device__ float g_vlo[(size_t)BATCH * S_LEN * EMB];   // V tf32 lo
__device__ float g_ctx[(size_t)BATCH * S_LEN * EMB];   // attention out (tf32-rounded)
__device__ float g_xr [(size_t)BATCH * S_LEN * EMB];   // rounded x
__device__ float g_wir[(size_t)3 * EMB * EMB];         // rounded in_proj_w
__device__ float g_wor[(size_t)EMB * EMB];             // rounded out_proj_w

// ===========================================================================
// Helpers
// ===========================================================================
__device__ __forceinline__ uint32_t smem_u32(const void* p) {
    uint32_t a;
    asm("{ .reg .u64 t; cvta.to.shared.u64 t, %1; cvt.u32.u64 %0, t; }"
        : "=r"(a) : "l"(p));
    return a;
}

__device__ __forceinline__ void cp_async16(uint32_t dst, const void* src) {
    asm volatile("cp.async.cg.shared.global [%0], [%1], 16;"
                 :: "r"(dst), "l"(src));
}
#define CP_COMMIT() asm volatile("cp.async.commit_group;")
#define CP_WAIT1()  asm volatile("cp.async.wait_group 1;")
#define CP_WAIT0()  asm volatile("cp.async.wait_group 0;")

__device__ __forceinline__ uint32_t f2tf32(float f) {
    uint32_t r;
    asm("cvt.rna.tf32.f32 %0, %1;" : "=r"(r) : "f"(f));
    return r;
}
__device__ __forceinline__ float rnd_tf32(float f) {
    return __uint_as_float(f2tf32(f));
}

// Split fp32 into tf32 hi + tf32 lo (3xTF32 error compensation)
__device__ __forceinline__ void tf32_split(float x, uint32_t& hi, uint32_t& lo) {
    hi = f2tf32(x);
    lo = f2tf32(x - __uint_as_float(hi));
}
__device__ __forceinline__ void tf32_split_f(float x, float& hi, float& lo) {
    uint32_t h, l;
    tf32_split(x, h, l);
    hi = __uint_as_float(h);
    lo = __uint_as_float(l);
}

// mma.sync m16n8k8 tf32: D += A*B, fp32 accumulate
__device__ __forceinline__ void mma_tf32(
    float* c, const uint32_t* a, const uint32_t* b)
{
    asm volatile(
        "mma.sync.aligned.m16n8k8.row.col.f32.tf32.tf32.f32 "
        "{%0,%1,%2,%3}, {%4,%5,%6,%7}, {%8,%9}, {%0,%1,%2,%3};"
        : "+f"(c[0]), "+f"(c[1]), "+f"(c[2]), "+f"(c[3])
        : "r"(a[0]), "r"(a[1]), "r"(a[2]), "r"(a[3]), "r"(b[0]), "r"(b[1]));
}

// ===========================================================================
// Elementwise tf32 pre-rounding (RNA). Idempotent; feeds GEMMs raw bits.
// ===========================================================================
__global__ __launch_bounds__(256) void round_tf32_kernel(
    const float4* __restrict__ src, float4* __restrict__ dst, int n4)
{
    for (int i = blockIdx.x * 256 + threadIdx.x; i < n4; i += gridDim.x * 256) {
        float4 v = src[i];
        v.x = rnd_tf32(v.x); v.y = rnd_tf32(v.y);
        v.z = rnd_tf32(v.z); v.w = rnd_tf32(v.w);
        dst[i] = v;
    }
}

// ===========================================================================
// tf32 tensor-core GEMM on PRE-ROUNDED inputs (unchanged from round 12):
//   C[M,N] = A[M,K] @ B[N,K]^T + bias[N]
// CTA 256x128, 8 warps as 4(M) x 2(N), warp tile 64x64.
// SPLIT MODE (gq != nullptr): N=3072 output routed per 1024-column region:
// Q -> gq (plain), K -> gkhi/gklo, V -> gvhi/gvlo (tf32 hi/lo).
// ===========================================================================
#define PAD      36
#define A_TILE_F (256 * PAD)
#define B_TILE_F (128 * PAD)
#define BUF_F    (A_TILE_F + B_TILE_F)
#define GM_SMEM  (2 * BUF_F * 4)               // 110592 bytes

__global__ __launch_bounds__(256) void gemm_mma(
    const float* __restrict__ A, const float* __restrict__ B,
    const float* __restrict__ bias, float* __restrict__ C,
    int M, int N, int K,
    float* __restrict__ gq,
    float* __restrict__ gkhi, float* __restrict__ gklo,
    float* __restrict__ gvhi, float* __restrict__ gvlo)
{
    extern __shared__ float smem[];
    const int tid  = threadIdx.x;
    const int wid  = tid >> 5;
    const int lane = tid & 31;
    const int wm   = wid >> 1;
    const int wn   = wid & 1;
    const int g    = lane >> 2;
    const int tig  = lane & 3;
    const int bm   = blockIdx.y * 256;
    const int bn   = blockIdx.x * 128;

    float acc[4][8][4];
    #pragma unroll
    for (int mt = 0; mt < 4; mt++)
        #pragma unroll
        for (int nt = 0; nt < 8; nt++)
            #pragma unroll
            for (int i = 0; i < 4; i++)
                acc[mt][nt][i] = 0.0f;

    auto fill = [&](int buf, int kc) {
        const int k0 = kc << 5;
        const uint32_t sA = smem_u32(smem + buf * BUF_F);
        const uint32_t sB = sA + A_TILE_F * 4;
        #pragma unroll
        for (int i = 0; i < 8; i++) {
            const int id = tid + (i << 8);
            const int r  = id >> 3;
            const int c  = id & 7;
            cp_async16(sA + (uint32_t)(r * PAD + c * 4) * 4,
                       A + (size_t)(bm + r) * K + k0 + c * 4);
        }
        #pragma unroll
        for (int i = 0; i < 4; i++) {
            const int id = tid + (i << 8);
            const int r  = id >> 3;
            const int c  = id & 7;
            cp_async16(sB + (uint32_t)(r * PAD + c * 4) * 4,
                       B + (size_t)(bn + r) * K + k0 + c * 4);
        }
        CP_COMMIT();
    };

    const int NK = K >> 5;
    fill(0, 0);
    fill(1, 1);

    for (int kc = 0; kc < NK; kc++) {
        const int buf = kc & 1;
        if (kc == NK - 1) { CP_WAIT0(); } else { CP_WAIT1(); }
        __syncthreads();

        const float* sA = smem + buf * BUF_F;
        const float* sB = sA + A_TILE_F;

        #pragma unroll
        for (int ks = 0; ks < 4; ks++) {
            const int kb = ks * 8 + tig;
            uint32_t af[4][4], bf[8][2];
            #pragma unroll
            for (int mt = 0; mt < 4; mt++) {
                const float* p = sA + (wm * 64 + mt * 16 + g) * PAD + kb;
                af[mt][0] = __float_as_uint(p[0]);
                af[mt][1] = __float_as_uint(p[8 * PAD]);
                af[mt][2] = __float_as_uint(p[4]);
                af[mt][3] = __float_as_uint(p[8 * PAD + 4]);
            }
            #pragma unroll
            for (int nt = 0; nt < 8; nt++) {
                const float* p = sB + (wn * 64 + nt * 8 + g) * PAD + kb;
                bf[nt][0] = __float_as_uint(p[0]);
                bf[nt][1] = __float_as_uint(p[4]);
            }
            #pragma unroll
            for (int mt = 0; mt < 4; mt++)
                #pragma unroll
                for (int nt = 0; nt < 8; nt++)
                    mma_tf32(acc[mt][nt], af[mt], bf[nt]);
        }
        __syncthreads();

        if (kc + 2 < NK) fill(buf, kc + 2);
    }

    // ---- epilogue ----
    const int region = (gq != nullptr) ? (bn >> 10) : -1;   // 0=Q, 1=K, 2=V
    #pragma unroll
    for (int mt = 0; mt < 4; mt++) {
        const int row0 = bm + wm * 64 + mt * 16 + g;
        #pragma unroll
        for (int nt = 0; nt < 8; nt++) {
            const int col = bn + wn * 64 + nt * 8 + 2 * tig;
            const float b0 = bias[col], b1 = bias[col + 1];
            float2 o0, o1;
            o0.x = acc[mt][nt][0] + b0;  o0.y = acc[mt][nt][1] + b1;
            o1.x = acc[mt][nt][2] + b0;  o1.y = acc[mt][nt][3] + b1;

            if (region < 0) {
                *(float2*)(C + (size_t)row0 * N + col)       = o0;
                *(float2*)(C + (size_t)(row0 + 8) * N + col) = o1;
            } else {
                const int lcol = col & 1023;
                const size_t i0 = (size_t)row0 * EMB + lcol;
                const size_t i1 = (size_t)(row0 + 8) * EMB + lcol;
                if (region == 0) {
                    *(float2*)(gq + i0) = o0;
                    *(float2*)(gq + i1) = o1;
                } else {
                    float2 h0, l0, h1, l1;
                    tf32_split_f(o0.x, h0.x, l0.x);
                    tf32_split_f(o0.y, h0.y, l0.y);
                    tf32_split_f(o1.x, h1.x, l1.x);
                    tf32_split_f(o1.y, h1.y, l1.y);
                    float* hi_dst = (region == 1) ? gkhi : gvhi;
                    float* lo_dst = (region == 1) ? gklo : gvlo;
                    *(float2*)(hi_dst + i0) = h0;
                    *(float2*)(lo_dst + i0) = l0;
                    *(float2*)(hi_dst + i1) = h1;
                    *(float2*)(lo_dst + i1) = l1;
                }
            }
        }
    }
}

// ===========================================================================
// Tensor-core flash attention, 3xTF32 compensated, pre-split K/V from global.
// RESHAPED for 2 CTAs/SM: CTA = 128 threads (4 warps) x 64 queries
// (16 q-rows/warp, per-warp role unchanged); key tiles of 32, KV double-
// buffered. Smem 87KB and <=256 regs/thread -> 2 co-resident CTAs whose
// softmax/fill phases overlap the other's mma stream.
// Mainloop math identical to round 12 (QK/PV 3xTF32, k-permuted PV).
// ===========================================================================
#define AP        68                            // padded row (floats)
#define QT_F      (64 * AP)                     // 4352 floats (64 queries)
#define KVT_F     (32 * AP)                     // 2176 floats (32 keys)
#define A_KHI     QT_F
#define A_KLO     (QT_F + 2 * KVT_F)
#define A_VHI     (QT_F + 4 * KVT_F)
#define A_VLO     (QT_F + 6 * KVT_F)
#define ATT_SMEM  ((QT_F + 8 * KVT_F) * 4)      // 87040 bytes

__global__ __launch_bounds__(128, 2) void attn_mma_kernel(
    const float* __restrict__ gq,
    const float* __restrict__ gkhi, const float* __restrict__ gklo,
    const float* __restrict__ gvhi, const float* __restrict__ gvlo,
    float* __restrict__ ctx)
{
    extern __shared__ float smem[];
    const int tid  = threadIdx.x;
    const int w    = tid >> 5;          // 0..3
    const int lane = tid & 31;
    const int g    = lane >> 2;
    const int tig  = lane & 3;

    const int qt = gridDim.x - 1 - blockIdx.x;     // heaviest tiles first, qt 0..31
    const int bh = blockIdx.y;
    const int b  = bh >> 4;
    const int h  = bh & 15;

    const size_t bbase = (size_t)b * S_LEN * EMB + h * DH;
    const int ktmax = 2 * qt + 1;                  // 32-key tiles

    // ---- issue Q stage (64 rows x 16 float4; bundled with first KV fill) ----
    {
        const float* Qsrc = gq + bbase + (size_t)(qt * 64) * EMB;
        const uint32_t qs = smem_u32(smem);
        #pragma unroll
        for (int i = 0; i < 8; i++) {
            const int id = tid + (i << 7);
            const int r = id >> 4, c4 = id & 15;
            cp_async16(qs + (uint32_t)((r * AP + c4 * 4) * 4),
                       Qsrc + (size_t)r * EMB + c4 * 4);
        }
    }

    auto fill_kv = [&](int buf, int kt) {
        const size_t tbase = bbase + (size_t)(kt * 32) * EMB;
        const uint32_t kh = smem_u32(smem + A_KHI + buf * KVT_F);
        const uint32_t kl = smem_u32(smem + A_KLO + buf * KVT_F);
        const uint32_t vh = smem_u32(smem + A_VHI + buf * KVT_F);
        const uint32_t vl = smem_u32(smem + A_VLO + buf * KVT_F);
        #pragma unroll
        for (int i = 0; i < 4; i++) {               // 32 rows x 16 float4 / 128 thr
            const int id = tid + (i << 7);
            const int r = id >> 4, c4 = id & 15;
            const uint32_t so = (uint32_t)((r * AP + c4 * 4) * 4);
            const size_t go = tbase + (size_t)r * EMB + c4 * 4;
            cp_async16(kh + so, gkhi + go);
            cp_async16(kl + so, gklo + go);
            cp_async16(vh + so, gvhi + go);
            cp_async16(vl + so, gvlo + go);
        }
        CP_COMMIT();
    };

    fill_kv(0, 0);          // group: Q + KV(0)
    fill_kv(1, 1);          // ktmax >= 1 always

    uint32_t Qh[8][4], Ql[8][4];
    float S[4][4];          // 32 keys = 4 n8 fragments
    float O[8][4];          // d = 64  = 8 n8 fragments
    float m0 = -1e30f, m1 = -1e30f, l0 = 0.0f, l1 = 0.0f;
    #pragma unroll
    for (int nt = 0; nt < 8; nt++)
        #pragma unroll
        for (int i = 0; i < 4; i++)
            O[nt][i] = 0.0f;

    for (int kt = 0; kt <= ktmax; kt++) {
        if (kt < ktmax) { CP_WAIT1(); } else { CP_WAIT0(); }
        __syncthreads();

        const int buf = kt & 1;

        if (kt == 0) {   // Q fragments, split into tf32 hi/lo once
            const float* Qp = smem + (16 * w + g) * AP + tig;
            #pragma unroll
            for (int kb = 0; kb < 8; kb++) {
                tf32_split(Qp[kb * 8],              Qh[kb][0], Ql[kb][0]);
                tf32_split(Qp[8 * AP + kb * 8],     Qh[kb][1], Ql[kb][1]);
                tf32_split(Qp[kb * 8 + 4],          Qh[kb][2], Ql[kb][2]);
                tf32_split(Qp[8 * AP + kb * 8 + 4], Qh[kb][3], Ql[kb][3]);
            }
        }

        const float* Khl = smem + A_KHI + buf * KVT_F + g * AP + tig;
        const float* Kll = smem + A_KLO + buf * KVT_F + g * AP + tig;
        const float* Vhl = smem + A_VHI + buf * KVT_F + 2 * tig * AP + g;
        const float* Vll = smem + A_VLO + buf * KVT_F + 2 * tig * AP + g;

        // ---- S = Q K^T (3xTF32), 4 n8 key fragments ----
        #pragma unroll
        for (int nt = 0; nt < 4; nt++)
            #pragma unroll
            for (int i = 0; i < 4; i++)
                S[nt][i] = 0.0f;

        #pragma unroll
        for (int kb = 0; kb < 8; kb++) {
            #pragma unroll
            for (int nt = 0; nt < 4; nt++) {
                const int so = nt * (8 * AP) + kb * 8;
                uint32_t bh_[2], bl_[2];
                bh_[0] = __float_as_uint(Khl[so]);
                bh_[1] = __float_as_uint(Khl[so + 4]);
                bl_[0] = __float_as_uint(Kll[so]);
                bl_[1] = __float_as_uint(Kll[so + 4]);
                mma_tf32(S[nt], Qh[kb], bh_);
                mma_tf32(S[nt], Qh[kb], bl_);
                mma_tf32(S[nt], Ql[kb], bh_);
            }
        }

        // ---- causal mask (diagonal region: last two 32-key tiles) ----
        if (kt >= 2 * qt) {
            const int q0 = 16 * w + g;
            const int q1 = q0 + 8;
            const int kb0 = (kt - 2 * qt) * 32;
            #pragma unroll
            for (int nt = 0; nt < 4; nt++) {
                const int kc = kb0 + nt * 8 + 2 * tig;
                if (kc     > q0) S[nt][0] = -1e30f;
                if (kc + 1 > q0) S[nt][1] = -1e30f;
                if (kc     > q1) S[nt][2] = -1e30f;
                if (kc + 1 > q1) S[nt][3] = -1e30f;
            }
        }

        // ---- online softmax (scale 0.125 folded into exp) ----
        float t0 = -1e30f, t1 = -1e30f;
        #pragma unroll
        for (int nt = 0; nt < 4; nt++) {
            t0 = fmaxf(t0, fmaxf(S[nt][0], S[nt][1]));
            t1 = fmaxf(t1, fmaxf(S[nt][2], S[nt][3]));
        }
        #pragma unroll
        for (int o = 1; o <= 2; o <<= 1) {
            t0 = fmaxf(t0, __shfl_xor_sync(0xffffffffu, t0, o));
            t1 = fmaxf(t1, __shfl_xor_sync(0xffffffffu, t1, o));
        }
        const float mn0 = fmaxf(m0, t0), mn1 = fmaxf(m1, t1);
        const float c0 = __expf(0.125f * (m0 - mn0));
        const float c1 = __expf(0.125f * (m1 - mn1));
        m0 = mn0; m1 = mn1;

        float rs0 = 0.0f, rs1 = 0.0f;
        #pragma unroll
        for (int nt = 0; nt < 4; nt++) {
            S[nt][0] = __expf(0.125f * (S[nt][0] - mn0));
            S[nt][1] = __expf(0.125f * (S[nt][1] - mn0));
            S[nt][2] = __expf(0.125f * (S[nt][2] - mn1));
            S[nt][3] = __expf(0.125f * (S[nt][3] - mn1));
            rs0 += S[nt][0] + S[nt][1];
            rs1 += S[nt][2] + S[nt][3];
        }
        #pragma unroll
        for (int o = 1; o <= 2; o <<= 1) {
            rs0 += __shfl_xor_sync(0xffffffffu, rs0, o);
            rs1 += __shfl_xor_sync(0xffffffffu, rs1, o);
        }
        l0 = l0 * c0 + rs0;
        l1 = l1 * c1 + rs1;

        #pragma unroll
        for (int nt = 0; nt < 8; nt++) {
            O[nt][0] *= c0; O[nt][1] *= c0;
            O[nt][2] *= c1; O[nt][3] *= c1;
        }

        // ---- O += P V (3-term compensated; k-permuted layout) ----
        #pragma unroll
        for (int kb = 0; kb < 4; kb++) {
            uint32_t aPh[4], aPl[4];
            tf32_split(S[kb][0], aPh[0], aPl[0]);
            tf32_split(S[kb][2], aPh[1], aPl[1]);
            tf32_split(S[kb][1], aPh[2], aPl[2]);
            tf32_split(S[kb][3], aPh[3], aPl[3]);
            #pragma unroll
            for (int nt = 0; nt < 8; nt++) {
                const int so = kb * (8 * AP) + nt * 8;
                uint32_t bh_[2], bl_[2];
                bh_[0] = __float_as_uint(Vhl[so]);
                bh_[1] = __float_as_uint(Vhl[so + AP]);
                bl_[0] = __float_as_uint(Vll[so]);
                bl_[1] = __float_as_uint(Vll[so + AP]);
                mma_tf32(O[nt], aPh, bh_);
                mma_tf32(O[nt], aPl, bh_);
                mma_tf32(O[nt], aPh, bl_);
            }
        }

        __syncthreads();   // all readers done before refill of this buffer
        if (kt + 2 <= ktmax) fill_kv(buf, kt + 2);
    }

    // ---- normalize + tf32-round + write ctx (gemm2 reads raw bits) ----
    const float i0 = 1.0f / l0, i1 = 1.0f / l1;
    const size_t row0 = (size_t)b * S_LEN + qt * 64 + 16 * w + g;
    #pragma unroll
    for (int nt = 0; nt < 8; nt++) {
        const int col = h * DH + nt * 8 + 2 * tig;
        float2 o0, o1;
        o0.x = rnd_tf32(O[nt][0] * i0);  o0.y = rnd_tf32(O[nt][1] * i0);
        o1.x = rnd_tf32(O[nt][2] * i1);  o1.y = rnd_tf32(O[nt][3] * i1);
        *(float2*)(ctx + row0 * EMB + col)       = o0;
        *(float2*)(ctx + (row0 + 8) * EMB + col) = o1;
    }
}

// ===========================================================================
// Launch: pre-round -> gemm1 (split epilogue) -> attention -> gemm2
// ===========================================================================
extern "C" void kernel_launch(void* const* d_in, const int* in_sizes, int n_in,
                              void* d_out, int out_size)
{
    const float* x     = (const float*)d_in[0];
    const float* w_in  = (const float*)d_in[1];
    const float* b_in  = (const float*)d_in[2];
    const float* w_out = (const float*)d_in[3];
    const float* b_out = (const float*)d_in[4];
    float* out = (float*)d_out;

    float *gq, *gkhi, *gklo, *gvhi, *gvlo, *ctx, *xr, *wir, *wor;
    cudaGetSymbolAddress((void**)&gq,   g_q);
    cudaGetSymbolAddress((void**)&gkhi, g_khi);
    cudaGetSymbolAddress((void**)&gklo, g_klo);
    cudaGetSymbolAddress((void**)&gvhi, g_vhi);
    cudaGetSymbolAddress((void**)&gvlo, g_vlo);
    cudaGetSymbolAddress((void**)&ctx,  g_ctx);
    cudaGetSymbolAddress((void**)&xr,   g_xr);
    cudaGetSymbolAddress((void**)&wir,  g_wir);
    cudaGetSymbolAddress((void**)&wor,  g_wor);

    const int M = BATCH * S_LEN;   // 4096

    static bool attr_set = false;
    if (!attr_set) {
        cudaFuncSetAttribute(gemm_mma,
                             cudaFuncAttributeMaxDynamicSharedMemorySize, GM_SMEM);
        cudaFuncSetAttribute(attn_mma_kernel,
                             cudaFuncAttributeMaxDynamicSharedMemorySize, ATT_SMEM);
        attr_set = true;
    }

    // 0) pre-round GEMM operands to tf32 (RNA), once
    {
        const int nx = M * EMB / 4;            // 1048576
        const int nw = 3 * EMB * EMB / 4;      // 786432
        const int no = EMB * EMB / 4;          // 262144
        round_tf32_kernel<<<1184, 256>>>((const float4*)x,     (float4*)xr,  nx);
        round_tf32_kernel<<<1184, 256>>>((const float4*)w_in,  (float4*)wir, nw);
        round_tf32_kernel<<<1184, 256>>>((const float4*)w_out, (float4*)wor, no);
    }

    // 1) qkv projection with split epilogue: Q plain, K/V tf32 hi+lo
    gemm_mma<<<dim3((3 * EMB) / 128, M / 256), 256, GM_SMEM>>>(
        xr, wir, b_in, nullptr, M, 3 * EMB, EMB,
        gq, gkhi, gklo, gvhi, gvlo);

    // 2) fused causal attention -> ctx [4096, 1024] (tf32-rounded)
    attn_mma_kernel<<<dim3(S_LEN / 64, BATCH * HEADS), 128, ATT_SMEM>>>(
        gq, gkhi, gklo, gvhi, gvlo, ctx);

    // 3) out = ctx @ out_proj_w^T + out_proj_b   [4096, 1024]
    gemm_mma<<<dim3(EMB / 128, M / 256), 256, GM_SMEM>>>(
        ctx, wor, b_out, out, M, EMB, EMB,
        nullptr, nullptr, nullptr, nullptr, nullptr);
}

// round 14
// speedup vs baseline: 1.1590x; 1.0150x over previous
#include <cuda_runtime.h>
#include <cstdint>

// Problem constants
#define S_LEN 2048
#define EMB   1024
#define HEADS 16
#define DH    64
#define BATCH 2

// Scratch (no allocations allowed)
__device__ float g_q  [(size_t)BATCH * S_LEN * EMB];   // Q (fp32)
__device__ float g_khi[(size_t)BATCH * S_LEN * EMB];   // K tf32 hi
__device__ float g_klo[(size_t)BATCH * S_LEN * EMB];   // K tf32 lo
__device__ float g_vhi[(size_t)BATCH * S_LEN * EMB];   // V tf32 hi
__device__ float g_vlo[(size_t)BATCH * S_LEN * EMB];   // V tf32 lo
__device__ float g_ctx[(size_t)BATCH * S_LEN * EMB];   // attention out (tf32-rounded)
__device__ float g_xr [(size_t)BATCH * S_LEN * EMB];   // rounded x
__device__ float g_wir[(size_t)3 * EMB * EMB];         // rounded in_proj_w
__device__ float g_wor[(size_t)EMB * EMB];             // rounded out_proj_w

// ===========================================================================
// Helpers
// ===========================================================================
__device__ __forceinline__ uint32_t smem_u32(const void* p) {
    uint32_t a;
    asm("{ .reg .u64 t; cvta.to.shared.u64 t, %1; cvt.u32.u64 %0, t; }"
        : "=r"(a) : "l"(p));
    return a;
}

__device__ __forceinline__ void cp_async16(uint32_t dst, const void* src) {
    asm volatile("cp.async.cg.shared.global [%0], [%1], 16;"
                 :: "r"(dst), "l"(src));
}
#define CP_COMMIT() asm volatile("cp.async.commit_group;")
#define CP_WAIT1()  asm volatile("cp.async.wait_group 1;")
#define CP_WAIT0()  asm volatile("cp.async.wait_group 0;")

__device__ __forceinline__ uint32_t f2tf32(float f) {
    uint32_t r;
    asm("cvt.rna.tf32.f32 %0, %1;" : "=r"(r) : "f"(f));
    return r;
}
__device__ __forceinline__ float rnd_tf32(float f) {
    return __uint_as_float(f2tf32(f));
}

// Split fp32 into tf32 hi + tf32 lo (3xTF32 error compensation)
__device__ __forceinline__ void tf32_split(float x, uint32_t& hi, uint32_t& lo) {
    hi = f2tf32(x);
    lo = f2tf32(x - __uint_as_float(hi));
}
__device__ __forceinline__ void tf32_split_f(float x, float& hi, float& lo) {
    uint32_t h, l;
    tf32_split(x, h, l);
    hi = __uint_as_float(h);
    lo = __uint_as_float(l);
}

// mma.sync m16n8k8 tf32: D += A*B, fp32 accumulate
__device__ __forceinline__ void mma_tf32(
    float* c, const uint32_t* a, const uint32_t* b)
{
    asm volatile(
        "mma.sync.aligned.m16n8k8.row.col.f32.tf32.tf32.f32 "
        "{%0,%1,%2,%3}, {%4,%5,%6,%7}, {%8,%9}, {%0,%1,%2,%3};"
        : "+f"(c[0]), "+f"(c[1]), "+f"(c[2]), "+f"(c[3])
        : "r"(a[0]), "r"(a[1]), "r"(a[2]), "r"(a[3]), "r"(b[0]), "r"(b[1]));
}

// ===========================================================================
// Elementwise tf32 pre-rounding (RNA). Idempotent; feeds GEMMs raw bits.
// ===========================================================================
__global__ __launch_bounds__(256) void round_tf32_kernel(
    const float4* __restrict__ src, float4* __restrict__ dst, int n4)
{
    for (int i = blockIdx.x * 256 + threadIdx.x; i < n4; i += gridDim.x * 256) {
        float4 v = src[i];
        v.x = rnd_tf32(v.x); v.y = rnd_tf32(v.y);
        v.z = rnd_tf32(v.z); v.w = rnd_tf32(v.w);
        dst[i] = v;
    }
}

// ===========================================================================
// tf32 tensor-core GEMM on PRE-ROUNDED inputs (unchanged from round 12):
//   C[M,N] = A[M,K] @ B[N,K]^T + bias[N]
// CTA 256x128, 8 warps as 4(M) x 2(N), warp tile 64x64.
// SPLIT MODE (gq != nullptr): N=3072 output routed per 1024-column region:
// Q -> gq (plain), K -> gkhi/gklo, V -> gvhi/gvlo (tf32 hi/lo).
// ===========================================================================
#define PAD      36
#define A_TILE_F (256 * PAD)
#define B_TILE_F (128 * PAD)
#define BUF_F    (A_TILE_F + B_TILE_F)
#define GM_SMEM  (2 * BUF_F * 4)               // 110592 bytes

__global__ __launch_bounds__(256) void gemm_mma(
    const float* __restrict__ A, const float* __restrict__ B,
    const float* __restrict__ bias, float* __restrict__ C,
    int M, int N, int K,
    float* __restrict__ gq,
    float* __restrict__ gkhi, float* __restrict__ gklo,
    float* __restrict__ gvhi, float* __restrict__ gvlo)
{
    extern __shared__ float smem[];
    const int tid  = threadIdx.x;
    const int wid  = tid >> 5;
    const int lane = tid & 31;
    const int wm   = wid >> 1;
    const int wn   = wid & 1;
    const int g    = lane >> 2;
    const int tig  = lane & 3;
    const int bm   = blockIdx.y * 256;
    const int bn   = blockIdx.x * 128;

    float acc[4][8][4];
    #pragma unroll
    for (int mt = 0; mt < 4; mt++)
        #pragma unroll
        for (int nt = 0; nt < 8; nt++)
            #pragma unroll
            for (int i = 0; i < 4; i++)
                acc[mt][nt][i] = 0.0f;

    auto fill = [&](int buf, int kc) {
        const int k0 = kc << 5;
        const uint32_t sA = smem_u32(smem + buf * BUF_F);
        const uint32_t sB = sA + A_TILE_F * 4;
        #pragma unroll
        for (int i = 0; i < 8; i++) {
            const int id = tid + (i << 8);
            const int r  = id >> 3;
            const int c  = id & 7;
            cp_async16(sA + (uint32_t)(r * PAD + c * 4) * 4,
                       A + (size_t)(bm + r) * K + k0 + c * 4);
        }
        #pragma unroll
        for (int i = 0; i < 4; i++) {
            const int id = tid + (i << 8);
            const int r  = id >> 3;
            const int c  = id & 7;
            cp_async16(sB + (uint32_t)(r * PAD + c * 4) * 4,
                       B + (size_t)(bn + r) * K + k0 + c * 4);
        }
        CP_COMMIT();
    };

    const int NK = K >> 5;
    fill(0, 0);
    fill(1, 1);

    for (int kc = 0; kc < NK; kc++) {
        const int buf = kc & 1;
        if (kc == NK - 1) { CP_WAIT0(); } else { CP_WAIT1(); }
        __syncthreads();

        const float* sA = smem + buf * BUF_F;
        const float* sB = sA + A_TILE_F;

        #pragma unroll
        for (int ks = 0; ks < 4; ks++) {
            const int kb = ks * 8 + tig;
            uint32_t af[4][4], bf[8][2];
            #pragma unroll
            for (int mt = 0; mt < 4; mt++) {
                const float* p = sA + (wm * 64 + mt * 16 + g) * PAD + kb;
                af[mt][0] = __float_as_uint(p[0]);
                af[mt][1] = __float_as_uint(p[8 * PAD]);
                af[mt][2] = __float_as_uint(p[4]);
                af[mt][3] = __float_as_uint(p[8 * PAD + 4]);
            }
            #pragma unroll
            for (int nt = 0; nt < 8; nt++) {
                const float* p = sB + (wn * 64 + nt * 8 + g) * PAD + kb;
                bf[nt][0] = __float_as_uint(p[0]);
                bf[nt][1] = __float_as_uint(p[4]);
            }
            #pragma unroll
            for (int mt = 0; mt < 4; mt++)
                #pragma unroll
                for (int nt = 0; nt < 8; nt++)
                    mma_tf32(acc[mt][nt], af[mt], bf[nt]);
        }
        __syncthreads();

        if (kc + 2 < NK) fill(buf, kc + 2);
    }

    // ---- epilogue ----
    const int region = (gq != nullptr) ? (bn >> 10) : -1;   // 0=Q, 1=K, 2=V
    #pragma unroll
    for (int mt = 0; mt < 4; mt++) {
        const int row0 = bm + wm * 64 + mt * 16 + g;
        #pragma unroll
        for (int nt = 0; nt < 8; nt++) {
            const int col = bn + wn * 64 + nt * 8 + 2 * tig;
            const float b0 = bias[col], b1 = bias[col + 1];
            float2 o0, o1;
            o0.x = acc[mt][nt][0] + b0;  o0.y = acc[mt][nt][1] + b1;
            o1.x = acc[mt][nt][2] + b0;  o1.y = acc[mt][nt][3] + b1;

            if (region < 0) {
                *(float2*)(C + (size_t)row0 * N + col)       = o0;
                *(float2*)(C + (size_t)(row0 + 8) * N + col) = o1;
            } else {
                const int lcol = col & 1023;
                const size_t i0 = (size_t)row0 * EMB + lcol;
                const size_t i1 = (size_t)(row0 + 8) * EMB + lcol;
                if (region == 0) {
                    *(float2*)(gq + i0) = o0;
                    *(float2*)(gq + i1) = o1;
                } else {
                    float2 h0, l0, h1, l1;
                    tf32_split_f(o0.x, h0.x, l0.x);
                    tf32_split_f(o0.y, h0.y, l0.y);
                    tf32_split_f(o1.x, h1.x, l1.x);
                    tf32_split_f(o1.y, h1.y, l1.y);
                    float* hi_dst = (region == 1) ? gkhi : gvhi;
                    float* lo_dst = (region == 1) ? gklo : gvlo;
                    *(float2*)(hi_dst + i0) = h0;
                    *(float2*)(lo_dst + i0) = l0;
                    *(float2*)(hi_dst + i1) = h1;
                    *(float2*)(lo_dst + i1) = l1;
                }
            }
        }
    }
}

// ===========================================================================
// Tensor-core flash attention, 3xTF32 compensated, pre-split K/V from global.
// 2 CTAs/SM AND 64-key tiles: CTA = 128 threads (4 warps) x 64 queries,
// single-buffered KV (Q 17KB + KV 70KB = 87KB -> 2 co-resident CTAs).
// The per-tile KV load wait is hidden by the PEER CTA's mma stream; softmax
// passes halve vs round 13 (17 vs 33 per query). Diagonal = one masked tile.
// Mainloop math identical (QK/PV 3xTF32, k-permuted PV).
// ===========================================================================
#define AP        68                            // padded row (floats)
#define QT_F      (64 * AP)                     // 4352 floats (64 queries)
#define KVT_F     (64 * AP)                     // 4352 floats (64 keys)
#define A_KHI     QT_F
#define A_KLO     (QT_F + 1 * KVT_F)
#define A_VHI     (QT_F + 2 * KVT_F)
#define A_VLO     (QT_F + 3 * KVT_F)
#define ATT_SMEM  ((QT_F + 4 * KVT_F) * 4)      // 87040 bytes

__global__ __launch_bounds__(128, 2) void attn_mma_kernel(
    const float* __restrict__ gq,
    const float* __restrict__ gkhi, const float* __restrict__ gklo,
    const float* __restrict__ gvhi, const float* __restrict__ gvlo,
    float* __restrict__ ctx)
{
    extern __shared__ float smem[];
    const int tid  = threadIdx.x;
    const int w    = tid >> 5;          // 0..3
    const int lane = tid & 31;
    const int g    = lane >> 2;
    const int tig  = lane & 3;

    const int qt = gridDim.x - 1 - blockIdx.x;     // heaviest tiles first, qt 0..31
    const int bh = blockIdx.y;
    const int b  = bh >> 4;
    const int h  = bh & 15;

    const size_t bbase = (size_t)b * S_LEN * EMB + h * DH;
    const int ktmax = qt;                           // 64-key tiles

    // ---- Q stage (64 rows x 16 float4; bundled with first KV fill) ----
    {
        const float* Qsrc = gq + bbase + (size_t)(qt * 64) * EMB;
        const uint32_t qs = smem_u32(smem);
        #pragma unroll
        for (int i = 0; i < 8; i++) {
            const int id = tid + (i << 7);
            const int r = id >> 4, c4 = id & 15;
            cp_async16(qs + (uint32_t)((r * AP + c4 * 4) * 4),
                       Qsrc + (size_t)r * EMB + c4 * 4);
        }
    }

    auto fill_kv = [&](int kt) {
        const size_t tbase = bbase + (size_t)(kt * 64) * EMB;
        const uint32_t kh = smem_u32(smem + A_KHI);
        const uint32_t kl = smem_u32(smem + A_KLO);
        const uint32_t vh = smem_u32(smem + A_VHI);
        const uint32_t vl = smem_u32(smem + A_VLO);
        #pragma unroll
        for (int i = 0; i < 8; i++) {               // 64 rows x 16 float4 / 128 thr
            const int id = tid + (i << 7);
            const int r = id >> 4, c4 = id & 15;
            const uint32_t so = (uint32_t)((r * AP + c4 * 4) * 4);
            const size_t go = tbase + (size_t)r * EMB + c4 * 4;
            cp_async16(kh + so, gkhi + go);
            cp_async16(kl + so, gklo + go);
            cp_async16(vh + so, gvhi + go);
            cp_async16(vl + so, gvlo + go);
        }
        CP_COMMIT();
    };

    fill_kv(0);          // one group: Q + KV(0)

    uint32_t Qh[8][4], Ql[8][4];
    float S[8][4];       // 64 keys = 8 n8 fragments
    float O[8][4];       // d = 64   = 8 n8 fragments
    float m0 = -1e30f, m1 = -1e30f, l0 = 0.0f, l1 = 0.0f;
    #pragma unroll
    for (int nt = 0; nt < 8; nt++)
        #pragma unroll
        for (int i = 0; i < 4; i++)
            O[nt][i] = 0.0f;

    for (int kt = 0; kt <= ktmax; kt++) {
        CP_WAIT0();
        __syncthreads();   // KV(kt) landed; peer CTA's mma hides this wait

        if (kt == 0) {   // Q fragments, split into tf32 hi/lo once
            const float* Qp = smem + (16 * w + g) * AP + tig;
            #pragma unroll
            for (int kb = 0; kb < 8; kb++) {
                tf32_split(Qp[kb * 8],              Qh[kb][0], Ql[kb][0]);
                tf32_split(Qp[8 * AP + kb * 8],     Qh[kb][1], Ql[kb][1]);
                tf32_split(Qp[kb * 8 + 4],          Qh[kb][2], Ql[kb][2]);
                tf32_split(Qp[8 * AP + kb * 8 + 4], Qh[kb][3], Ql[kb][3]);
            }
        }

        const float* Khl = smem + A_KHI + g * AP + tig;
        const float* Kll = smem + A_KLO + g * AP + tig;
        const float* Vhl = smem + A_VHI + 2 * tig * AP + g;
        const float* Vll = smem + A_VLO + 2 * tig * AP + g;

        // ---- S = Q K^T (3xTF32), 8 n8 key fragments ----
        #pragma unroll
        for (int nt = 0; nt < 8; nt++)
            #pragma unroll
            for (int i = 0; i < 4; i++)
                S[nt][i] = 0.0f;

        #pragma unroll
        for (int kb = 0; kb < 8; kb++) {
            #pragma unroll
            for (int nt = 0; nt < 8; nt++) {
                const int so = nt * (8 * AP) + kb * 8;
                uint32_t bh_[2], bl_[2];
                bh_[0] = __float_as_uint(Khl[so]);
                bh_[1] = __float_as_uint(Khl[so + 4]);
                bl_[0] = __float_as_uint(Kll[so]);
                bl_[1] = __float_as_uint(Kll[so + 4]);
                mma_tf32(S[nt], Qh[kb], bh_);
                mma_tf32(S[nt], Qh[kb], bl_);
                mma_tf32(S[nt], Ql[kb], bh_);
            }
        }

        // ---- causal mask (single diagonal tile) ----
        if (kt == qt) {
            const int q0 = 16 * w + g;
            const int q1 = q0 + 8;
            #pragma unroll
            for (int nt = 0; nt < 8; nt++) {
                const int kc = nt * 8 + 2 * tig;
                if (kc     > q0) S[nt][0] = -1e30f;
                if (kc + 1 > q0) S[nt][1] = -1e30f;
                if (kc     > q1) S[nt][2] = -1e30f;
                if (kc + 1 > q1) S[nt][3] = -1e30f;
            }
        }

        // ---- online softmax (scale 0.125 folded into exp) ----
        float t0 = -1e30f, t1 = -1e30f;
        #pragma unroll
        for (int nt = 0; nt < 8; nt++) {
            t0 = fmaxf(t0, fmaxf(S[nt][0], S[nt][1]));
            t1 = fmaxf(t1, fmaxf(S[nt][2], S[nt][3]));
        }
        #pragma unroll
        for (int o = 1; o <= 2; o <<= 1) {
            t0 = fmaxf(t0, __shfl_xor_sync(0xffffffffu, t0, o));
            t1 = fmaxf(t1, __shfl_xor_sync(0xffffffffu, t1, o));
        }
        const float mn0 = fmaxf(m0, t0), mn1 = fmaxf(m1, t1);
        const float c0 = __expf(0.125f * (m0 - mn0));
        const float c1 = __expf(0.125f * (m1 - mn1));
        m0 = mn0; m1 = mn1;

        float rs0 = 0.0f, rs1 = 0.0f;
        #pragma unroll
        for (int nt = 0; nt < 8; nt++) {
            S[nt][0] = __expf(0.125f * (S[nt][0] - mn0));
            S[nt][1] = __expf(0.125f * (S[nt][1] - mn0));
            S[nt][2] = __expf(0.125f * (S[nt][2] - mn1));
            S[nt][3] = __expf(0.125f * (S[nt][3] - mn1));
            rs0 += S[nt][0] + S[nt][1];
            rs1 += S[nt][2] + S[nt][3];
        }
        #pragma unroll
        for (int o = 1; o <= 2; o <<= 1) {
            rs0 += __shfl_xor_sync(0xffffffffu, rs0, o);
            rs1 += __shfl_xor_sync(0xffffffffu, rs1, o);
        }
        l0 = l0 * c0 + rs0;
        l1 = l1 * c1 + rs1;

        #pragma unroll
        for (int nt = 0; nt < 8; nt++) {
            O[nt][0] *= c0; O[nt][1] *= c0;
            O[nt][2] *= c1; O[nt][3] *= c1;
        }

        // ---- O += P V (3-term compensated; k-permuted layout) ----
        #pragma unroll
        for (int kb = 0; kb < 8; kb++) {
            uint32_t aPh[4], aPl[4];
            tf32_split(S[kb][0], aPh[0], aPl[0]);
            tf32_split(S[kb][2], aPh[1], aPl[1]);
            tf32_split(S[kb][1], aPh[2], aPl[2]);
            tf32_split(S[kb][3], aPh[3], aPl[3]);
            #pragma unroll
            for (int nt = 0; nt < 8; nt++) {
                const int so = kb * (8 * AP) + nt * 8;
                uint32_t bh_[2], bl_[2];
                bh_[0] = __float_as_uint(Vhl[so]);
                bh_[1] = __float_as_uint(Vhl[so + AP]);
                bl_[0] = __float_as_uint(Vll[so]);
                bl_[1] = __float_as_uint(Vll[so + AP]);
                mma_tf32(O[nt], aPh, bh_);
                mma_tf32(O[nt], aPl, bh_);
                mma_tf32(O[nt], aPh, bl_);
            }
        }

        __syncthreads();   // all readers done before single-buffer refill
        if (kt < ktmax) fill_kv(kt + 1);
    }

    // ---- normalize + tf32-round + write ctx (gemm2 reads raw bits) ----
    const float i0 = 1.0f / l0, i1 = 1.0f / l1;
    const size_t row0 = (size_t)b * S_LEN + qt * 64 + 16 * w + g;
    #pragma unroll
    for (int nt = 0; nt < 8; nt++) {
        const int col = h * DH + nt * 8 + 2 * tig;
        float2 o0, o1;
        o0.x = rnd_tf32(O[nt][0] * i0);  o0.y = rnd_tf32(O[nt][1] * i0);
        o1.x = rnd_tf32(O[nt][2] * i1);  o1.y = rnd_tf32(O[nt][3] * i1);
        *(float2*)(ctx + row0 * EMB + col)       = o0;
        *(float2*)(ctx + (row0 + 8) * EMB + col) = o1;
    }
}

// ===========================================================================
// Launch: pre-round -> gemm1 (split epilogue) -> attention -> gemm2
// ===========================================================================
extern "C" void kernel_launch(void* const* d_in, const int* in_sizes, int n_in,
                              void* d_out, int out_size)
{
    const float* x     = (const float*)d_in[0];
    const float* w_in  = (const float*)d_in[1];
    const float* b_in  = (const float*)d_in[2];
    const float* w_out = (const float*)d_in[3];
    const float* b_out = (const float*)d_in[4];
    float* out = (float*)d_out;

    float *gq, *gkhi, *gklo, *gvhi, *gvlo, *ctx, *xr, *wir, *wor;
    cudaGetSymbolAddress((void**)&gq,   g_q);
    cudaGetSymbolAddress((void**)&gkhi, g_khi);
    cudaGetSymbolAddress((void**)&gklo, g_klo);
    cudaGetSymbolAddress((void**)&gvhi, g_vhi);
    cudaGetSymbolAddress((void**)&gvlo, g_vlo);
    cudaGetSymbolAddress((void**)&ctx,  g_ctx);
    cudaGetSymbolAddress((void**)&xr,   g_xr);
    cudaGetSymbolAddress((void**)&wir,  g_wir);
    cudaGetSymbolAddress((void**)&wor,  g_wor);

    const int M = BATCH * S_LEN;   // 4096

    static bool attr_set = false;
    if (!attr_set) {
        cudaFuncSetAttribute(gemm_mma,
                             cudaFuncAttributeMaxDynamicSharedMemorySize, GM_SMEM);
        cudaFuncSetAttribute(attn_mma_kernel,
                             cudaFuncAttributeMaxDynamicSharedMemorySize, ATT_SMEM);
        attr_set = true;
    }

    // 0) pre-round GEMM operands to tf32 (RNA), once
    {
        const int nx = M * EMB / 4;            // 1048576
        const int nw = 3 * EMB * EMB / 4;      // 786432
        const int no = EMB * EMB / 4;          // 262144
        round_tf32_kernel<<<1184, 256>>>((const float4*)x,     (float4*)xr,  nx);
        round_tf32_kernel<<<1184, 256>>>((const float4*)w_in,  (float4*)wir, nw);
        round_tf32_kernel<<<1184, 256>>>((const float4*)w_out, (float4*)wor, no);
    }

    // 1) qkv projection with split epilogue: Q plain, K/V tf32 hi+lo
    gemm_mma<<<dim3((3 * EMB) / 128, M / 256), 256, GM_SMEM>>>(
        xr, wir, b_in, nullptr, M, 3 * EMB, EMB,
        gq, gkhi, gklo, gvhi, gvlo);

    // 2) fused causal attention -> ctx [4096, 1024] (tf32-rounded)
    attn_mma_kernel<<<dim3(S_LEN / 64, BATCH * HEADS), 128, ATT_SMEM>>>(
        gq, gkhi, gklo, gvhi, gvlo, ctx);

    // 3) out = ctx @ out_proj_w^T + out_proj_b   [4096, 1024]
    gemm_mma<<<dim3(EMB / 128, M / 256), 256, GM_SMEM>>>(
        ctx, wor, b_out, out, M, EMB, EMB,
        nullptr, nullptr, nullptr, nullptr, nullptr);
}

// round 15
// speedup vs baseline: 1.1730x; 1.0121x over previous
#include <cuda_runtime.h>
#include <cstdint>

// Problem constants
#define S_LEN 2048
#define EMB   1024
#define HEADS 16
#define DH    64
#define BATCH 2

// Scratch (no allocations allowed)
__device__ float g_q  [(size_t)BATCH * S_LEN * EMB];   // Q (fp32)
__device__ float g_khi[(size_t)BATCH * S_LEN * EMB];   // K tf32 hi
__device__ float g_klo[(size_t)BATCH * S_LEN * EMB];   // K tf32 lo
__device__ float g_vhi[(size_t)BATCH * S_LEN * EMB];   // V tf32 hi
__device__ float g_vlo[(size_t)BATCH * S_LEN * EMB];   // V tf32 lo
__device__ float g_ctx[(size_t)BATCH * S_LEN * EMB];   // attention out (tf32-rounded)
__device__ float g_xr [(size_t)BATCH * S_LEN * EMB];   // rounded x
__device__ float g_wir[(size_t)3 * EMB * EMB];         // rounded in_proj_w
__device__ float g_wor[(size_t)EMB * EMB];             // rounded out_proj_w

// ===========================================================================
// Helpers
// ===========================================================================
__device__ __forceinline__ uint32_t smem_u32(const void* p) {
    uint32_t a;
    asm("{ .reg .u64 t; cvta.to.shared.u64 t, %1; cvt.u32.u64 %0, t; }"
        : "=r"(a) : "l"(p));
    return a;
}

__device__ __forceinline__ void cp_async16(uint32_t dst, const void* src) {
    asm volatile("cp.async.cg.shared.global [%0], [%1], 16;"
                 :: "r"(dst), "l"(src));
}
#define CP_COMMIT() asm volatile("cp.async.commit_group;")
#define CP_WAIT0()  asm volatile("cp.async.wait_group 0;")

__device__ __forceinline__ uint32_t f2tf32(float f) {
    uint32_t r;
    asm("cvt.rna.tf32.f32 %0, %1;" : "=r"(r) : "f"(f));
    return r;
}
__device__ __forceinline__ float rnd_tf32(float f) {
    return __uint_as_float(f2tf32(f));
}

// Split fp32 into tf32 hi + tf32 lo (3xTF32 error compensation)
__device__ __forceinline__ void tf32_split(float x, uint32_t& hi, uint32_t& lo) {
    hi = f2tf32(x);
    lo = f2tf32(x - __uint_as_float(hi));
}
__device__ __forceinline__ void tf32_split_f(float x, float& hi, float& lo) {
    uint32_t h, l;
    tf32_split(x, h, l);
    hi = __uint_as_float(h);
    lo = __uint_as_float(l);
}

// mma.sync m16n8k8 tf32: D += A*B, fp32 accumulate
__device__ __forceinline__ void mma_tf32(
    float* c, const uint32_t* a, const uint32_t* b)
{
    asm volatile(
        "mma.sync.aligned.m16n8k8.row.col.f32.tf32.tf32.f32 "
        "{%0,%1,%2,%3}, {%4,%5,%6,%7}, {%8,%9}, {%0,%1,%2,%3};"
        : "+f"(c[0]), "+f"(c[1]), "+f"(c[2]), "+f"(c[3])
        : "r"(a[0]), "r"(a[1]), "r"(a[2]), "r"(a[3]), "r"(b[0]), "r"(b[1]));
}

// ===========================================================================
// Merged elementwise tf32 pre-rounding (RNA) for x, w_in, w_out in ONE launch.
// ===========================================================================
__global__ __launch_bounds__(256) void round3_tf32_kernel(
    const float4* __restrict__ s0, float4* __restrict__ d0, int n0,
    const float4* __restrict__ s1, float4* __restrict__ d1, int n1,
    const float4* __restrict__ s2, float4* __restrict__ d2, int n2)
{
    const int total = n0 + n1 + n2;
    for (int i = blockIdx.x * 256 + threadIdx.x; i < total; i += gridDim.x * 256) {
        const float4* s;
        float4* d;
        int j = i;
        if (j < n0)           { s = s0; d = d0; }
        else if ((j -= n0) < n1) { s = s1; d = d1; }
        else                  { j -= n1; s = s2; d = d2; }
        float4 v = s[j];
        v.x = rnd_tf32(v.x); v.y = rnd_tf32(v.y);
        v.z = rnd_tf32(v.z); v.w = rnd_tf32(v.w);
        d[j] = v;
    }
}

// ===========================================================================
// tf32 tensor-core GEMM on PRE-ROUNDED inputs:
//   C[M,N] = A[M,K] @ B[N,K]^T + bias[N]
// NEW: CTA = 128 threads, 128x128 tile, 4 warps as 2(M) x 2(N), warp 64x64
// (per-warp inner loop identical to round 14). K-chunk 32, SINGLE-buffered
// 36KB smem -> 2 CTAs/SM; the peer CTA hides the per-chunk load latency
// (same pattern that works in the attention kernel). 16 warps/SM doubles
// mma latency hiding vs the old 8.
// SPLIT MODE (gq != nullptr): N=3072 output routed per 1024-column region:
// Q -> gq (plain), K -> gkhi/gklo, V -> gvhi/gvlo (tf32 hi/lo).
// ===========================================================================
#define PAD      36
#define GT_ROWS  128
#define TILE_F_G (GT_ROWS * PAD)               // 4608 floats per tile
#define GBUF_F   (2 * TILE_F_G)                // A + B = 9216 floats
#define GM_SMEM  (GBUF_F * 4)                  // 36864 bytes (single stage)

__global__ __launch_bounds__(128, 2) void gemm_mma(
    const float* __restrict__ A, const float* __restrict__ B,
    const float* __restrict__ bias, float* __restrict__ C,
    int M, int N, int K,
    float* __restrict__ gq,
    float* __restrict__ gkhi, float* __restrict__ gklo,
    float* __restrict__ gvhi, float* __restrict__ gvlo)
{
    extern __shared__ float smem[];
    const int tid  = threadIdx.x;
    const int wid  = tid >> 5;        // 0..3
    const int lane = tid & 31;
    const int wm   = wid >> 1;        // 0..1 -> 64-row band
    const int wn   = wid & 1;         // 0..1 -> 64-col band
    const int g    = lane >> 2;
    const int tig  = lane & 3;
    const int bm   = blockIdx.y * 128;
    const int bn   = blockIdx.x * 128;

    float acc[4][8][4];
    #pragma unroll
    for (int mt = 0; mt < 4; mt++)
        #pragma unroll
        for (int nt = 0; nt < 8; nt++)
            #pragma unroll
            for (int i = 0; i < 4; i++)
                acc[mt][nt][i] = 0.0f;

    auto fill = [&](int kc) {
        const int k0 = kc << 5;
        const uint32_t sA = smem_u32(smem);
        const uint32_t sB = sA + TILE_F_G * 4;
        #pragma unroll
        for (int i = 0; i < 8; i++) {              // A: 128 rows x 8 float4
            const int id = tid + (i << 7);
            const int r  = id >> 3;
            const int c  = id & 7;
            cp_async16(sA + (uint32_t)(r * PAD + c * 4) * 4,
                       A + (size_t)(bm + r) * K + k0 + c * 4);
        }
        #pragma unroll
        for (int i = 0; i < 8; i++) {              // B: 128 rows x 8 float4
            const int id = tid + (i << 7);
            const int r  = id >> 3;
            const int c  = id & 7;
            cp_async16(sB + (uint32_t)(r * PAD + c * 4) * 4,
                       B + (size_t)(bn + r) * K + k0 + c * 4);
        }
        CP_COMMIT();
    };

    const int NK = K >> 5;
    fill(0);

    for (int kc = 0; kc < NK; kc++) {
        CP_WAIT0();
        __syncthreads();   // chunk landed; peer CTA's mma hides this wait

        const float* sA = smem;
        const float* sB = smem + TILE_F_G;

        #pragma unroll
        for (int ks = 0; ks < 4; ks++) {
            const int kb = ks * 8 + tig;
            uint32_t af[4][4], bf[8][2];
            #pragma unroll
            for (int mt = 0; mt < 4; mt++) {
                const float* p = sA + (wm * 64 + mt * 16 + g) * PAD + kb;
                af[mt][0] = __float_as_uint(p[0]);
                af[mt][1] = __float_as_uint(p[8 * PAD]);
                af[mt][2] = __float_as_uint(p[4]);
                af[mt][3] = __float_as_uint(p[8 * PAD + 4]);
            }
            #pragma unroll
            for (int nt = 0; nt < 8; nt++) {
                const float* p = sB + (wn * 64 + nt * 8 + g) * PAD + kb;
                bf[nt][0] = __float_as_uint(p[0]);
                bf[nt][1] = __float_as_uint(p[4]);
            }
            #pragma unroll
            for (int mt = 0; mt < 4; mt++)
                #pragma unroll
                for (int nt = 0; nt < 8; nt++)
                    mma_tf32(acc[mt][nt], af[mt], bf[nt]);
        }
        __syncthreads();   // all reads done before single-buffer refill

        if (kc + 1 < NK) fill(kc + 1);
    }

    // ---- epilogue ----
    const int region = (gq != nullptr) ? (bn >> 10) : -1;   // 0=Q, 1=K, 2=V
    #pragma unroll
    for (int mt = 0; mt < 4; mt++) {
        const int row0 = bm + wm * 64 + mt * 16 + g;
        #pragma unroll
        for (int nt = 0; nt < 8; nt++) {
            const int col = bn + wn * 64 + nt * 8 + 2 * tig;
            const float b0 = bias[col], b1 = bias[col + 1];
            float2 o0, o1;
            o0.x = acc[mt][nt][0] + b0;  o0.y = acc[mt][nt][1] + b1;
            o1.x = acc[mt][nt][2] + b0;  o1.y = acc[mt][nt][3] + b1;

            if (region < 0) {
                *(float2*)(C + (size_t)row0 * N + col)       = o0;
                *(float2*)(C + (size_t)(row0 + 8) * N + col) = o1;
            } else {
                const int lcol = col & 1023;
                const size_t i0 = (size_t)row0 * EMB + lcol;
                const size_t i1 = (size_t)(row0 + 8) * EMB + lcol;
                if (region == 0) {
                    *(float2*)(gq + i0) = o0;
                    *(float2*)(gq + i1) = o1;
                } else {
                    float2 h0, l0, h1, l1;
                    tf32_split_f(o0.x, h0.x, l0.x);
                    tf32_split_f(o0.y, h0.y, l0.y);
                    tf32_split_f(o1.x, h1.x, l1.x);
                    tf32_split_f(o1.y, h1.y, l1.y);
                    float* hi_dst = (region == 1) ? gkhi : gvhi;
                    float* lo_dst = (region == 1) ? gklo : gvlo;
                    *(float2*)(hi_dst + i0) = h0;
                    *(float2*)(lo_dst + i0) = l0;
                    *(float2*)(hi_dst + i1) = h1;
                    *(float2*)(lo_dst + i1) = l1;
                }
            }
        }
    }
}

// ===========================================================================
// Tensor-core flash attention, 3xTF32 compensated, pre-split K/V from global.
// UNCHANGED from round 14 (best-known): 2 CTAs/SM, 128 threads x 64 queries,
// 64-key tiles, single-buffered KV; peer CTA hides the per-tile load wait.
// ===========================================================================
#define AP        68                            // padded row (floats)
#define QT_F      (64 * AP)                     // 4352 floats (64 queries)
#define KVT_F     (64 * AP)                     // 4352 floats (64 keys)
#define A_KHI     QT_F
#define A_KLO     (QT_F + 1 * KVT_F)
#define A_VHI     (QT_F + 2 * KVT_F)
#define A_VLO     (QT_F + 3 * KVT_F)
#define ATT_SMEM  ((QT_F + 4 * KVT_F) * 4)      // 87040 bytes

__global__ __launch_bounds__(128, 2) void attn_mma_kernel(
    const float* __restrict__ gq,
    const float* __restrict__ gkhi, const float* __restrict__ gklo,
    const float* __restrict__ gvhi, const float* __restrict__ gvlo,
    float* __restrict__ ctx)
{
    extern __shared__ float smem[];
    const int tid  = threadIdx.x;
    const int w    = tid >> 5;          // 0..3
    const int lane = tid & 31;
    const int g    = lane >> 2;
    const int tig  = lane & 3;

    const int qt = gridDim.x - 1 - blockIdx.x;     // heaviest tiles first, qt 0..31
    const int bh = blockIdx.y;
    const int b  = bh >> 4;
    const int h  = bh & 15;

    const size_t bbase = (size_t)b * S_LEN * EMB + h * DH;
    const int ktmax = qt;                           // 64-key tiles

    // ---- Q stage (64 rows x 16 float4; bundled with first KV fill) ----
    {
        const float* Qsrc = gq + bbase + (size_t)(qt * 64) * EMB;
        const uint32_t qs = smem_u32(smem);
        #pragma unroll
        for (int i = 0; i < 8; i++) {
            const int id = tid + (i << 7);
            const int r = id >> 4, c4 = id & 15;
            cp_async16(qs + (uint32_t)((r * AP + c4 * 4) * 4),
                       Qsrc + (size_t)r * EMB + c4 * 4);
        }
    }

    auto fill_kv = [&](int kt) {
        const size_t tbase = bbase + (size_t)(kt * 64) * EMB;
        const uint32_t kh = smem_u32(smem + A_KHI);
        const uint32_t kl = smem_u32(smem + A_KLO);
        const uint32_t vh = smem_u32(smem + A_VHI);
        const uint32_t vl = smem_u32(smem + A_VLO);
        #pragma unroll
        for (int i = 0; i < 8; i++) {               // 64 rows x 16 float4 / 128 thr
            const int id = tid + (i << 7);
            const int r = id >> 4, c4 = id & 15;
            const uint32_t so = (uint32_t)((r * AP + c4 * 4) * 4);
            const size_t go = tbase + (size_t)r * EMB + c4 * 4;
            cp_async16(kh + so, gkhi + go);
            cp_async16(kl + so, gklo + go);
            cp_async16(vh + so, gvhi + go);
            cp_async16(vl + so, gvlo + go);
        }
        CP_COMMIT();
    };

    fill_kv(0);          // one group: Q + KV(0)

    uint32_t Qh[8][4], Ql[8][4];
    float S[8][4];       // 64 keys = 8 n8 fragments
    float O[8][4];       // d = 64   = 8 n8 fragments
    float m0 = -1e30f, m1 = -1e30f, l0 = 0.0f, l1 = 0.0f;
    #pragma unroll
    for (int nt = 0; nt < 8; nt++)
        #pragma unroll
        for (int i = 0; i < 4; i++)
            O[nt][i] = 0.0f;

    for (int kt = 0; kt <= ktmax; kt++) {
        CP_WAIT0();
        __syncthreads();   // KV(kt) landed; peer CTA's mma hides this wait

        if (kt == 0) {   // Q fragments, split into tf32 hi/lo once
            const float* Qp = smem + (16 * w + g) * AP + tig;
            #pragma unroll
            for (int kb = 0; kb < 8; kb++) {
                tf32_split(Qp[kb * 8],              Qh[kb][0], Ql[kb][0]);
                tf32_split(Qp[8 * AP + kb * 8],     Qh[kb][1], Ql[kb][1]);
                tf32_split(Qp[kb * 8 + 4],          Qh[kb][2], Ql[kb][2]);
                tf32_split(Qp[8 * AP + kb * 8 + 4], Qh[kb][3], Ql[kb][3]);
            }
        }

        const float* Khl = smem + A_KHI + g * AP + tig;
        const float* Kll = smem + A_KLO + g * AP + tig;
        const float* Vhl = smem + A_VHI + 2 * tig * AP + g;
        const float* Vll = smem + A_VLO + 2 * tig * AP + g;

        // ---- S = Q K^T (3xTF32), 8 n8 key fragments ----
        #pragma unroll
        for (int nt = 0; nt < 8; nt++)
            #pragma unroll
            for (int i = 0; i < 4; i++)
                S[nt][i] = 0.0f;

        #pragma unroll
        for (int kb = 0; kb < 8; kb++) {
            #pragma unroll
            for (int nt = 0; nt < 8; nt++) {
                const int so = nt * (8 * AP) + kb * 8;
                uint32_t bh_[2], bl_[2];
                bh_[0] = __float_as_uint(Khl[so]);
                bh_[1] = __float_as_uint(Khl[so + 4]);
                bl_[0] = __float_as_uint(Kll[so]);
                bl_[1] = __float_as_uint(Kll[so + 4]);
                mma_tf32(S[nt], Qh[kb], bh_);
                mma_tf32(S[nt], Qh[kb], bl_);
                mma_tf32(S[nt], Ql[kb], bh_);
            }
        }

        // ---- causal mask (single diagonal tile) ----
        if (kt == qt) {
            const int q0 = 16 * w + g;
            const int q1 = q0 + 8;
            #pragma unroll
            for (int nt = 0; nt < 8; nt++) {
                const int kc = nt * 8 + 2 * tig;
                if (kc     > q0) S[nt][0] = -1e30f;
                if (kc + 1 > q0) S[nt][1] = -1e30f;
                if (kc     > q1) S[nt][2] = -1e30f;
                if (kc + 1 > q1) S[nt][3] = -1e30f;
            }
        }

        // ---- online softmax (scale 0.125 folded into exp) ----
        float t0 = -1e30f, t1 = -1e30f;
        #pragma unroll
        for (int nt = 0; nt < 8; nt++) {
            t0 = fmaxf(t0, fmaxf(S[nt][0], S[nt][1]));
            t1 = fmaxf(t1, fmaxf(S[nt][2], S[nt][3]));
        }
        #pragma unroll
        for (int o = 1; o <= 2; o <<= 1) {
            t0 = fmaxf(t0, __shfl_xor_sync(0xffffffffu, t0, o));
            t1 = fmaxf(t1, __shfl_xor_sync(0xffffffffu, t1, o));
        }
        const float mn0 = fmaxf(m0, t0), mn1 = fmaxf(m1, t1);
        const float c0 = __expf(0.125f * (m0 - mn0));
        const float c1 = __expf(0.125f * (m1 - mn1));
        m0 = mn0; m1 = mn1;

        float rs0 = 0.0f, rs1 = 0.0f;
        #pragma unroll
        for (int nt = 0; nt < 8; nt++) {
            S[nt][0] = __expf(0.125f * (S[nt][0] - mn0));
            S[nt][1] = __expf(0.125f * (S[nt][1] - mn0));
            S[nt][2] = __expf(0.125f * (S[nt][2] - mn1));
            S[nt][3] = __expf(0.125f * (S[nt][3] - mn1));
            rs0 += S[nt][0] + S[nt][1];
            rs1 += S[nt][2] + S[nt][3];
        }
        #pragma unroll
        for (int o = 1; o <= 2; o <<= 1) {
            rs0 += __shfl_xor_sync(0xffffffffu, rs0, o);
            rs1 += __shfl_xor_sync(0xffffffffu, rs1, o);
        }
        l0 = l0 * c0 + rs0;
        l1 = l1 * c1 + rs1;

        #pragma unroll
        for (int nt = 0; nt < 8; nt++) {
            O[nt][0] *= c0; O[nt][1] *= c0;
            O[nt][2] *= c1; O[nt][3] *= c1;
        }

        // ---- O += P V (3-term compensated; k-permuted layout) ----
        #pragma unroll
        for (int kb = 0; kb < 8; kb++) {
            uint32_t aPh[4], aPl[4];
            tf32_split(S[kb][0], aPh[0], aPl[0]);
            tf32_split(S[kb][2], aPh[1], aPl[1]);
            tf32_split(S[kb][1], aPh[2], aPl[2]);
            tf32_split(S[kb][3], aPh[3], aPl[3]);
            #pragma unroll
            for (int nt = 0; nt < 8; nt++) {
                const int so = kb * (8 * AP) + nt * 8;
                uint32_t bh_[2], bl_[2];
                bh_[0] = __float_as_uint(Vhl[so]);
                bh_[1] = __float_as_uint(Vhl[so + AP]);
                bl_[0] = __float_as_uint(Vll[so]);
                bl_[1] = __float_as_uint(Vll[so + AP]);
                mma_tf32(O[nt], aPh, bh_);
                mma_tf32(O[nt], aPl, bh_);
                mma_tf32(O[nt], aPh, bl_);
            }
        }

        __syncthreads();   // all readers done before single-buffer refill
        if (kt < ktmax) fill_kv(kt + 1);
    }

    // ---- normalize + tf32-round + write ctx (gemm2 reads raw bits) ----
    const float i0 = 1.0f / l0, i1 = 1.0f / l1;
    const size_t row0 = (size_t)b * S_LEN + qt * 64 + 16 * w + g;
    #pragma unroll
    for (int nt = 0; nt < 8; nt++) {
        const int col = h * DH + nt * 8 + 2 * tig;
        float2 o0, o1;
        o0.x = rnd_tf32(O[nt][0] * i0);  o0.y = rnd_tf32(O[nt][1] * i0);
        o1.x = rnd_tf32(O[nt][2] * i1);  o1.y = rnd_tf32(O[nt][3] * i1);
        *(float2*)(ctx + row0 * EMB + col)       = o0;
        *(float2*)(ctx + (row0 + 8) * EMB + col) = o1;
    }
}

// ===========================================================================
// Launch: merged pre-round -> gemm1 (split epilogue) -> attention -> gemm2
// ===========================================================================
extern "C" void kernel_launch(void* const* d_in, const int* in_sizes, int n_in,
                              void* d_out, int out_size)
{
    const float* x     = (const float*)d_in[0];
    const float* w_in  = (const float*)d_in[1];
    const float* b_in  = (const float*)d_in[2];
    const float* w_out = (const float*)d_in[3];
    const float* b_out = (const float*)d_in[4];
    float* out = (float*)d_out;

    float *gq, *gkhi, *gklo, *gvhi, *gvlo, *ctx, *xr, *wir, *wor;
    cudaGetSymbolAddress((void**)&gq,   g_q);
    cudaGetSymbolAddress((void**)&gkhi, g_khi);
    cudaGetSymbolAddress((void**)&gklo, g_klo);
    cudaGetSymbolAddress((void**)&gvhi, g_vhi);
    cudaGetSymbolAddress((void**)&gvlo, g_vlo);
    cudaGetSymbolAddress((void**)&ctx,  g_ctx);
    cudaGetSymbolAddress((void**)&xr,   g_xr);
    cudaGetSymbolAddress((void**)&wir,  g_wir);
    cudaGetSymbolAddress((void**)&wor,  g_wor);

    const int M = BATCH * S_LEN;   // 4096

    static bool attr_set = false;
    if (!attr_set) {
        cudaFuncSetAttribute(gemm_mma,
                             cudaFuncAttributeMaxDynamicSharedMemorySize, GM_SMEM);
        cudaFuncSetAttribute(attn_mma_kernel,
                             cudaFuncAttributeMaxDynamicSharedMemorySize, ATT_SMEM);
        attr_set = true;
    }

    // 0) pre-round x, w_in, w_out to tf32 (RNA), one merged launch
    {
        const int nx = M * EMB / 4;            // 1048576
        const int nw = 3 * EMB * EMB / 4;      // 786432
        const int no = EMB * EMB / 4;          // 262144
        round3_tf32_kernel<<<1184, 256>>>(
            (const float4*)x,     (float4*)xr,  nx,
            (const float4*)w_in,  (float4*)wir, nw,
            (const float4*)w_out, (float4*)wor, no);
    }

    // 1) qkv projection with split epilogue: Q plain, K/V tf32 hi+lo
    gemm_mma<<<dim3((3 * EMB) / 128, M / 128), 128, GM_SMEM>>>(
        xr, wir, b_in, nullptr, M, 3 * EMB, EMB,
        gq, gkhi, gklo, gvhi, gvlo);

    // 2) fused causal attention -> ctx [4096, 1024] (tf32-rounded)
    attn_mma_kernel<<<dim3(S_LEN / 64, BATCH * HEADS), 128, ATT_SMEM>>>(
        gq, gkhi, gklo, gvhi, gvlo, ctx);

    // 3) out = ctx @ out_proj_w^T + out_proj_b   [4096, 1024]
    gemm_mma<<<dim3(EMB / 128, M / 128), 128, GM_SMEM>>>(
        ctx, wor, b_out, out, M, EMB, EMB,
        nullptr, nullptr, nullptr, nullptr, nullptr);
}